// round 5
// baseline (speedup 1.0000x reference)
#include <cuda_runtime.h>
#include <cuda_bf16.h>
#include <cstdint>

#define BATCH 8
#define SLEN  2048
#define DIM   1024
#define WIN   20
#define MTOT  (BATCH * SLEN)   // 16384

// ---------------- static device scratch -------------------------------------
__device__ int8_t        g_q8h [(size_t)MTOT * DIM];  // Q fixed-point hi/lo s8 planes
__device__ int8_t        g_q8l [(size_t)MTOT * DIM];
__device__ int8_t        g_w8h [(size_t)DIM * DIM];   // W^T fixed-point planes: [d][j]
__device__ int8_t        g_w8l [(size_t)DIM * DIM];
__device__ __nv_bfloat16 g_qthi[(size_t)MTOT * DIM];  // QT = Q@W, bf16 split
__device__ __nv_bfloat16 g_qtlo[(size_t)MTOT * DIM];
__device__ __nv_bfloat16 g_khi [(size_t)MTOT * DIM];  // keys bf16 split
__device__ __nv_bfloat16 g_klo [(size_t)MTOT * DIM];

// ---------------- helpers ----------------------------------------------------
__device__ __forceinline__ uint32_t smem_u32(const void* p) {
    uint32_t a;
    asm("{ .reg .u64 t; cvta.to.shared.u64 t, %1; cvt.u32.u64 %0, t; }" : "=r"(a) : "l"(p));
    return a;
}
#define CP_ASYNC16(sd, gp) \
    asm volatile("cp.async.cg.shared.global [%0], [%1], 16;" :: "r"(sd), "l"(gp) : "memory")
#define CP_COMMIT()   asm volatile("cp.async.commit_group;" ::: "memory")
#define CP_WAIT0()    asm volatile("cp.async.wait_group 0;" ::: "memory")
#define CP_WAIT1()    asm volatile("cp.async.wait_group 1;" ::: "memory")
#define ST_SHARED_ZERO16(a) \
    asm volatile("st.shared.v4.b32 [%0], {%1,%1,%1,%1};" :: "r"(a), "r"(0) : "memory")

__device__ __forceinline__ void ldsm_x4(uint32_t a, uint32_t& r0, uint32_t& r1,
                                        uint32_t& r2, uint32_t& r3) {
    asm volatile("ldmatrix.sync.aligned.m8n8.x4.shared.b16 {%0,%1,%2,%3}, [%4];"
                 : "=r"(r0), "=r"(r1), "=r"(r2), "=r"(r3) : "r"(a));
}
__device__ __forceinline__ void ldsm_x4_t(uint32_t a, uint32_t& r0, uint32_t& r1,
                                          uint32_t& r2, uint32_t& r3) {
    asm volatile("ldmatrix.sync.aligned.m8n8.x4.trans.shared.b16 {%0,%1,%2,%3}, [%4];"
                 : "=r"(r0), "=r"(r1), "=r"(r2), "=r"(r3) : "r"(a));
}
__device__ __forceinline__ void mma16816(float* c, const uint32_t* a,
                                         uint32_t b0, uint32_t b1) {
    asm volatile(
        "mma.sync.aligned.m16n8k16.row.col.f32.bf16.bf16.f32 "
        "{%0,%1,%2,%3}, {%4,%5,%6,%7}, {%8,%9}, {%0,%1,%2,%3};"
        : "+f"(c[0]), "+f"(c[1]), "+f"(c[2]), "+f"(c[3])
        : "r"(a[0]), "r"(a[1]), "r"(a[2]), "r"(a[3]), "r"(b0), "r"(b1));
}
__device__ __forceinline__ void imma16832(int* c, const uint32_t* a,
                                          uint32_t b0, uint32_t b1) {
    asm volatile(
        "mma.sync.aligned.m16n8k32.row.col.s32.s8.s8.s32 "
        "{%0,%1,%2,%3}, {%4,%5,%6,%7}, {%8,%9}, {%0,%1,%2,%3};"
        : "+r"(c[0]), "+r"(c[1]), "+r"(c[2]), "+r"(c[3])
        : "r"(a[0]), "r"(a[1]), "r"(a[2]), "r"(a[3]), "r"(b0), "r"(b1));
}

// ---------------- prep: Q -> fixed-point s8 hi/lo planes ----------------------
__global__ __launch_bounds__(256) void qquant_kernel(const float* __restrict__ Q) {
    size_t i = (size_t)blockIdx.x * 256 + threadIdx.x;   // handles 4 floats
    float4 v = ((const float4*)Q)[i];
    char h[4], l[4];
    float vv[4] = {v.x, v.y, v.z, v.w};
#pragma unroll
    for (int k = 0; k < 4; k++) {
        int q16 = __float2int_rn(fminf(fmaxf(vv[k] * 4064.0f, -32512.f), 32512.f));
        int qh = (q16 + 128) >> 8;
        int ql = q16 - (qh << 8);
        h[k] = (char)qh;
        l[k] = (char)ql;
    }
    *(char4*)(g_q8h + 4 * i) = make_char4(h[0], h[1], h[2], h[3]);
    *(char4*)(g_q8l + 4 * i) = make_char4(l[0], l[1], l[2], l[3]);
}

// ---------------- prep: W^T + fixed-point split --------------------------------
__global__ void wquant_kernel(const float* __restrict__ W) {
    __shared__ float t[32][33];
    int bx = blockIdx.x * 32;   // d
    int by = blockIdx.y * 32;   // j
    int tx = threadIdx.x, ty0 = threadIdx.y;
#pragma unroll
    for (int i = 0; i < 4; i++) {
        int ty = ty0 + i * 8;
        t[ty][tx] = W[(size_t)(by + ty) * DIM + bx + tx];
    }
    __syncthreads();
#pragma unroll
    for (int i = 0; i < 4; i++) {
        int ty = ty0 + i * 8;
        float v = t[tx][ty];                     // = W[by+tx][bx+ty]
        int w16 = __float2int_rn(fminf(fmaxf(v * 1040384.0f, -32512.f), 32512.f));
        int wh = (w16 + 128) >> 8;
        int wl = w16 - (wh << 8);
        size_t o = (size_t)(bx + ty) * DIM + by + tx;   // [d][j]
        g_w8h[o] = (char)wh;
        g_w8l[o] = (char)wl;
    }
}

// ---------------- prep: keys -> bf16 hi/lo split ------------------------------
__global__ __launch_bounds__(256) void ksplit_kernel(const float* __restrict__ src) {
    size_t i = (size_t)blockIdx.x * 256 + threadIdx.x;
    float4 v = ((const float4*)src)[i];
    __nv_bfloat16 hx = __float2bfloat16(v.x), hy = __float2bfloat16(v.y);
    __nv_bfloat16 hz = __float2bfloat16(v.z), hw = __float2bfloat16(v.w);
    __nv_bfloat16 lx = __float2bfloat16(v.x - __bfloat162float(hx));
    __nv_bfloat16 ly = __float2bfloat16(v.y - __bfloat162float(hy));
    __nv_bfloat16 lz = __float2bfloat16(v.z - __bfloat162float(hz));
    __nv_bfloat16 lw = __float2bfloat16(v.w - __bfloat162float(hw));
    ((__nv_bfloat162*)g_khi)[2 * i]     = __halves2bfloat162(hx, hy);
    ((__nv_bfloat162*)g_khi)[2 * i + 1] = __halves2bfloat162(hz, hw);
    ((__nv_bfloat162*)g_klo)[2 * i]     = __halves2bfloat162(lx, ly);
    ((__nv_bfloat162*)g_klo)[2 * i + 1] = __halves2bfloat162(lz, lw);
}

// ---------------- int8 IMMA GEMM: QT = Q @ W ----------------------------------
// CTA 128(m) x 64(n), 8 warps = 2m x 4n, warp tile 64x16.
// K chunked by 64, double-buffered. Per k32: 1 imma (qh*wh) into acc_hh,
// 2 imma (qh*wl, ql*wh) into acc_x. QT = hh/64516 + x/16516096.
#define KC2   64
#define ASTR  80                 // 64B row + 16B pad -> conflict-free ldsm
#define ATILE (128 * ASTR)       // 10240
#define BTILE (64 * ASTR)        // 5120
#define OFFAH 0
#define OFFAL ATILE
#define OFFBH (2 * ATILE)
#define OFFBL (2 * ATILE + BTILE)
#define STG2  (2 * ATILE + 2 * BTILE)   // 30720
#define SMEM_G2 (2 * STG2)              // 61440
#define NCH2  (DIM / KC2)               // 16

__device__ __forceinline__ void load_stage8(uint32_t sst,
                                            const int8_t* ah, const int8_t* al,
                                            const int8_t* bh, const int8_t* bl,
                                            int kc0, int tid) {
#pragma unroll
    for (int i = 0; i < 2; i++) {
        int flat = tid + i * 256;            // 0..511
        int r = flat >> 2, seg = flat & 3;
        size_t go = (size_t)r * DIM + kc0 + seg * 16;
        uint32_t so = (uint32_t)(r * ASTR + seg * 16);
        CP_ASYNC16(sst + OFFAH + so, ah + go);
        CP_ASYNC16(sst + OFFAL + so, al + go);
    }
    {
        int r = tid >> 2, seg = tid & 3;     // 64 rows x 4 segs
        size_t go = (size_t)r * DIM + kc0 + seg * 16;
        uint32_t so = (uint32_t)(r * ASTR + seg * 16);
        CP_ASYNC16(sst + OFFBH + so, bh + go);
        CP_ASYNC16(sst + OFFBL + so, bl + go);
    }
}

__global__ __launch_bounds__(256, 2) void qt_gemm_kernel() {
    extern __shared__ __align__(128) char smem[];
    const int tid  = threadIdx.x;
    const int wid  = tid >> 5, lane = tid & 31;
    const int bn   = blockIdx.x * 64;    // d tile
    const int bm   = blockIdx.y * 128;   // q tile
    const int wm   = (wid >> 2) * 64;
    const int wn   = (wid & 3) * 16;
    const uint32_t sb = smem_u32(smem);

    const int8_t* ah = g_q8h + (size_t)bm * DIM;
    const int8_t* al = g_q8l + (size_t)bm * DIM;
    const int8_t* bh = g_w8h + (size_t)bn * DIM;
    const int8_t* bl = g_w8l + (size_t)bn * DIM;

    int hh[4][2][4], xx[4][2][4];
#pragma unroll
    for (int i = 0; i < 4; i++)
#pragma unroll
        for (int j = 0; j < 2; j++)
#pragma unroll
            for (int k = 0; k < 4; k++) { hh[i][j][k] = 0; xx[i][j][k] = 0; }

    const uint32_t lmo = (uint32_t)((lane & 15) * ASTR + (lane >> 4) * 16);

    load_stage8(sb, ah, al, bh, bl, 0, tid);
    CP_COMMIT();

    for (int c = 0; c < NCH2; c++) {
        const uint32_t sst = sb + (c & 1) * STG2;
        if (c + 1 < NCH2) {
            load_stage8(sb + ((c + 1) & 1) * STG2, ah, al, bh, bl, (c + 1) * KC2, tid);
            CP_COMMIT();
            CP_WAIT1();
        } else {
            CP_WAIT0();
        }
        __syncthreads();

#pragma unroll
        for (int ks = 0; ks < 2; ks++) {
            const uint32_t ko = ks * 32;
            uint32_t af[4][4], alf[4][4], bf[4], blf[4];
#pragma unroll
            for (int mi = 0; mi < 4; mi++)
                ldsm_x4(sst + OFFAH + (wm + mi * 16) * ASTR + lmo + ko,
                        af[mi][0], af[mi][1], af[mi][2], af[mi][3]);
            ldsm_x4(sst + OFFBH + wn * ASTR + lmo + ko, bf[0], bf[1], bf[2], bf[3]);
            ldsm_x4(sst + OFFBL + wn * ASTR + lmo + ko, blf[0], blf[1], blf[2], blf[3]);
#pragma unroll
            for (int mi = 0; mi < 4; mi++)
#pragma unroll
                for (int ni = 0; ni < 2; ni++)
                    imma16832(hh[mi][ni], af[mi], bf[ni], bf[2 + ni]);
#pragma unroll
            for (int mi = 0; mi < 4; mi++)
                ldsm_x4(sst + OFFAL + (wm + mi * 16) * ASTR + lmo + ko,
                        alf[mi][0], alf[mi][1], alf[mi][2], alf[mi][3]);
#pragma unroll
            for (int mi = 0; mi < 4; mi++)
#pragma unroll
                for (int ni = 0; ni < 2; ni++)
                    imma16832(xx[mi][ni], af[mi], blf[ni], blf[2 + ni]);
#pragma unroll
            for (int mi = 0; mi < 4; mi++)
#pragma unroll
                for (int ni = 0; ni < 2; ni++)
                    imma16832(xx[mi][ni], alf[mi], bf[ni], bf[2 + ni]);
        }
        __syncthreads();
    }

    // epilogue: QT = hh*C1 + xx*C2, bf16 hi/lo split -> g_qthi/g_qtlo
    const float C1 = 1.0f / 64516.0f;           // SQ*SW*65536
    const float C2 = C1 * (1.0f / 256.0f);      // SQ*SW*256
    const int qr = lane >> 2, qc = (lane & 3) * 2;
#pragma unroll
    for (int mi = 0; mi < 4; mi++) {
#pragma unroll
        for (int ni = 0; ni < 2; ni++) {
            const int col = bn + wn + ni * 8 + qc;
#pragma unroll
            for (int half = 0; half < 2; half++) {
                const int row = bm + wm + mi * 16 + qr + half * 8;
                float v0 = (float)hh[mi][ni][half * 2] * C1 +
                           (float)xx[mi][ni][half * 2] * C2;
                float v1 = (float)hh[mi][ni][half * 2 + 1] * C1 +
                           (float)xx[mi][ni][half * 2 + 1] * C2;
                __nv_bfloat16 h0 = __float2bfloat16(v0);
                __nv_bfloat16 h1 = __float2bfloat16(v1);
                __nv_bfloat16 l0 = __float2bfloat16(v0 - __bfloat162float(h0));
                __nv_bfloat16 l1 = __float2bfloat16(v1 - __bfloat162float(h1));
                size_t o = ((size_t)row * DIM + col) / 2;
                ((__nv_bfloat162*)g_qthi)[o] = __halves2bfloat162(h0, h1);
                ((__nv_bfloat162*)g_qtlo)[o] = __halves2bfloat162(l0, l1);
            }
        }
    }
}

// ---------------- banded attention via mma.sync (validated R4) ----------------
#define QB2    64
#define KSTRB  144
#define PSTRB  240
#define SSTR   132

#define OFF_KH 0u
#define OFF_KL 18432u
#define OFF_QH 36864u
#define OFF_QL 46080u
#define OFF_S  0u
#define OFF_PH 55296u
#define OFF_PL 70656u
#define SMEM_B 86016u

__device__ __forceinline__ void load_ktile(uint32_t sb, int q0, size_t kbase,
                                           int dc, int tid) {
#pragma unroll
    for (int i = 0; i < 4; i++) {
        int flat = tid + i * 256;
        int r = flat >> 3, seg = flat & 7;
        int kr = q0 - WIN + r;
        uint32_t sh = sb + OFF_KH + (uint32_t)(r * KSTRB + seg * 16);
        uint32_t sl = sb + OFF_KL + (uint32_t)(r * KSTRB + seg * 16);
        if ((unsigned)kr < SLEN) {
            size_t go = kbase + (size_t)kr * DIM + dc + seg * 8;
            CP_ASYNC16(sh, g_khi + go);
            CP_ASYNC16(sl, g_klo + go);
        } else {
            ST_SHARED_ZERO16(sh);
            ST_SHARED_ZERO16(sl);
        }
    }
}

__global__ __launch_bounds__(256, 2) void band_attn_kernel(float* __restrict__ out) {
    extern __shared__ __align__(128) char smem[];
    const uint32_t sb = smem_u32(smem);
    const int tid = threadIdx.x, wid = tid >> 5, lane = tid & 31;
    const int b = blockIdx.y, q0 = blockIdx.x * QB2;
    const size_t kbase  = (size_t)b * SLEN * DIM;
    const size_t qtbase = ((size_t)b * SLEN + q0) * DIM;

    const int wm  = (wid >> 1) * 16;
    const int wn  = (wid & 1) * 64;
    const int wn3 = (wid & 1) * 32;

    float acc[8][4];
#pragma unroll
    for (int i = 0; i < 8; i++)
#pragma unroll
        for (int j = 0; j < 4; j++) acc[i][j] = 0.f;

    const uint32_t lmoA = (uint32_t)((wm + (lane & 15)) * KSTRB + (lane >> 4) * 16);
    const uint32_t lmoB = (uint32_t)((lane & 15) * KSTRB + (lane >> 4) * 16);

    for (int ch = 0; ch < 16; ch++) {
        const int dc = ch * 64;
#pragma unroll
        for (int i = 0; i < 2; i++) {
            int flat = tid + i * 256;
            int r = flat >> 3, seg = flat & 7;
            size_t go = qtbase + (size_t)r * DIM + dc + seg * 8;
            uint32_t so = (uint32_t)(r * KSTRB + seg * 16);
            CP_ASYNC16(sb + OFF_QH + so, g_qthi + go);
            CP_ASYNC16(sb + OFF_QL + so, g_qtlo + go);
        }
        load_ktile(sb, q0, kbase, dc, tid);
        CP_COMMIT();
        CP_WAIT0();
        __syncthreads();

#pragma unroll
        for (int ks = 0; ks < 4; ks++) {
            const uint32_t ko = ks * 32;
            uint32_t ah[4], al[4], bh[4][4], bl[4][4];
            ldsm_x4(sb + OFF_QH + lmoA + ko, ah[0], ah[1], ah[2], ah[3]);
            ldsm_x4(sb + OFF_QL + lmoA + ko, al[0], al[1], al[2], al[3]);
#pragma unroll
            for (int g = 0; g < 4; g++) {
                uint32_t ba = (uint32_t)((wn + g * 16) * KSTRB) + lmoB + ko;
                ldsm_x4(sb + OFF_KH + ba, bh[g][0], bh[g][1], bh[g][2], bh[g][3]);
                ldsm_x4(sb + OFF_KL + ba, bl[g][0], bl[g][1], bl[g][2], bl[g][3]);
            }
#pragma unroll
            for (int nf = 0; nf < 8; nf++) {
                int g = nf >> 1, p = nf & 1;
                mma16816(acc[nf], ah, bh[g][p], bh[g][2 + p]);
            }
#pragma unroll
            for (int nf = 0; nf < 8; nf++) {
                int g = nf >> 1, p = nf & 1;
                mma16816(acc[nf], ah, bl[g][p], bl[g][2 + p]);
            }
#pragma unroll
            for (int nf = 0; nf < 8; nf++) {
                int g = nf >> 1, p = nf & 1;
                mma16816(acc[nf], al, bh[g][p], bh[g][2 + p]);
            }
        }
        __syncthreads();
    }

    {
        float* S = (float*)(smem + OFF_S);
        int r0 = wm + (lane >> 2);
        int c0 = wn + (lane & 3) * 2;
#pragma unroll
        for (int nf = 0; nf < 8; nf++) {
            int c = c0 + nf * 8;
            *(float2*)&S[r0 * SSTR + c]       = make_float2(acc[nf][0], acc[nf][1]);
            *(float2*)&S[(r0 + 8) * SSTR + c] = make_float2(acc[nf][2], acc[nf][3]);
        }
    }
    __syncthreads();

    {
        float* S = (float*)(smem + OFF_S);
        __nv_bfloat16* PH = (__nv_bfloat16*)(smem + OFF_PH);
        __nv_bfloat16* PL = (__nv_bfloat16*)(smem + OFF_PL);
        const int row = tid >> 2, part = tid & 3;
        int rmin = row;
        int t = WIN - q0;
        if (t > rmin) rmin = t;
        int rmax = row + 2 * WIN;
        t = (SLEN - 1) + WIN - q0;
        if (t < rmax) rmax = t;
        const int cbeg = part * 32, cend = cbeg + 32;

        float mx = -3.4e38f;
        for (int c = cbeg; c < cend; c++)
            if (c >= rmin && c <= rmax) mx = fmaxf(mx, S[row * SSTR + c]);
        mx = fmaxf(mx, __shfl_xor_sync(0xFFFFFFFFu, mx, 1));
        mx = fmaxf(mx, __shfl_xor_sync(0xFFFFFFFFu, mx, 2));

        float sum = 0.f;
        for (int c = cbeg; c < cend; c++) {
            float e = (c >= rmin && c <= rmax) ? __expf(S[row * SSTR + c] - mx) : 0.f;
            S[row * SSTR + c] = e;
            sum += e;
        }
        sum += __shfl_xor_sync(0xFFFFFFFFu, sum, 1);
        sum += __shfl_xor_sync(0xFFFFFFFFu, sum, 2);
        const float inv = 1.f / sum;

        for (int c = cbeg; c < cend && c < 112; c++) {
            float p = S[row * SSTR + c] * inv;
            __nv_bfloat16 h = __float2bfloat16(p);
            __nv_bfloat16 l = __float2bfloat16(p - __bfloat162float(h));
            PH[row * 120 + c] = h;
            PL[row * 120 + c] = l;
        }
    }
    __syncthreads();

    const uint32_t lmoP = (uint32_t)((wm + (lane & 15)) * PSTRB + (lane >> 4) * 16);
    for (int ch = 0; ch < 16; ch++) {
        const int dc = ch * 64;
        load_ktile(sb, q0, kbase, dc, tid);
        CP_COMMIT();
        CP_WAIT0();
        __syncthreads();

        float oacc[4][4];
#pragma unroll
        for (int i = 0; i < 4; i++)
#pragma unroll
            for (int j = 0; j < 4; j++) oacc[i][j] = 0.f;

#pragma unroll
        for (int ks = 0; ks < 7; ks++) {
            uint32_t ah[4], al[4], bh[2][4], bl[2][4];
            ldsm_x4(sb + OFF_PH + lmoP + ks * 32, ah[0], ah[1], ah[2], ah[3]);
            ldsm_x4(sb + OFF_PL + lmoP + ks * 32, al[0], al[1], al[2], al[3]);
#pragma unroll
            for (int g = 0; g < 2; g++) {
                uint32_t ba = (uint32_t)((ks * 16 + (lane & 15)) * KSTRB +
                                         wn3 * 2 + g * 32 + (lane >> 4) * 16);
                ldsm_x4_t(sb + OFF_KH + ba, bh[g][0], bh[g][1], bh[g][2], bh[g][3]);
                ldsm_x4_t(sb + OFF_KL + ba, bl[g][0], bl[g][1], bl[g][2], bl[g][3]);
            }
#pragma unroll
            for (int nf = 0; nf < 4; nf++) {
                int g = nf >> 1, p = nf & 1;
                mma16816(oacc[nf], ah, bh[g][2 * p], bh[g][2 * p + 1]);
            }
#pragma unroll
            for (int nf = 0; nf < 4; nf++) {
                int g = nf >> 1, p = nf & 1;
                mma16816(oacc[nf], ah, bl[g][2 * p], bl[g][2 * p + 1]);
            }
#pragma unroll
            for (int nf = 0; nf < 4; nf++) {
                int g = nf >> 1, p = nf & 1;
                mma16816(oacc[nf], al, bh[g][2 * p], bh[g][2 * p + 1]);
            }
        }

        const int r0 = q0 + wm + (lane >> 2);
        const int c0 = dc + wn3 + (lane & 3) * 2;
#pragma unroll
        for (int nf = 0; nf < 4; nf++) {
            int c = c0 + nf * 8;
            *(float2*)(out + kbase + (size_t)r0 * DIM + c) =
                make_float2(oacc[nf][0], oacc[nf][1]);
            *(float2*)(out + kbase + (size_t)(r0 + 8) * DIM + c) =
                make_float2(oacc[nf][2], oacc[nf][3]);
        }
        __syncthreads();
    }
}

extern "C" void kernel_launch(void* const* d_in, const int* in_sizes, int n_in,
                              void* d_out, int out_size) {
    const float* queries = (const float*)d_in[0];
    const float* keys    = (const float*)d_in[1];
    const float* W       = (const float*)d_in[2];
    // d_in[3] = b_reduce: per-(b,q) constant added to all logits -> softmax-invariant, unused.
    float* out = (float*)d_out;

    cudaFuncSetAttribute(qt_gemm_kernel, cudaFuncAttributeMaxDynamicSharedMemorySize, SMEM_G2);
    cudaFuncSetAttribute(band_attn_kernel, cudaFuncAttributeMaxDynamicSharedMemorySize, SMEM_B);

    const int elemGrid = (MTOT * DIM) / 4 / 256;
    qquant_kernel<<<elemGrid, 256>>>(queries);
    ksplit_kernel<<<elemGrid, 256>>>(keys);
    wquant_kernel<<<dim3(DIM / 32, DIM / 32), dim3(32, 8)>>>(W);

    dim3 gg(DIM / 64, MTOT / 128);
    qt_gemm_kernel<<<gg, 256, SMEM_G2>>>();

    dim3 g2(SLEN / QB2, BATCH);
    band_attn_kernel<<<g2, 256, SMEM_B>>>(out);
}

// round 6
// speedup vs baseline: 2.3448x; 2.3448x over previous
#include <cuda_runtime.h>
#include <cuda_bf16.h>
#include <cuda_fp16.h>
#include <cstdint>

#define BATCH 8
#define SLEN  2048
#define DIM   1024
#define WIN   20
#define MTOT  (BATCH * SLEN)   // 16384

// ---------------- static device scratch -------------------------------------
__device__ __half        g_q16 [(size_t)MTOT * DIM];  // Q fp16 (single plane)
__device__ __half        g_w16h[(size_t)DIM * DIM];   // W^T fp16 hi: [d][j]
__device__ __half        g_w16l[(size_t)DIM * DIM];   // W^T fp16 residual
__device__ __nv_bfloat16 g_qthi[(size_t)MTOT * DIM];  // QT = Q@W, bf16 split
__device__ __nv_bfloat16 g_qtlo[(size_t)MTOT * DIM];
__device__ __nv_bfloat16 g_khi [(size_t)MTOT * DIM];  // keys bf16 split
__device__ __nv_bfloat16 g_klo [(size_t)MTOT * DIM];

// ---------------- helpers ----------------------------------------------------
__device__ __forceinline__ uint32_t smem_u32(const void* p) {
    uint32_t a;
    asm("{ .reg .u64 t; cvta.to.shared.u64 t, %1; cvt.u32.u64 %0, t; }" : "=r"(a) : "l"(p));
    return a;
}
#define CP_ASYNC16(sd, gp) \
    asm volatile("cp.async.cg.shared.global [%0], [%1], 16;" :: "r"(sd), "l"(gp) : "memory")
#define CP_COMMIT()   asm volatile("cp.async.commit_group;" ::: "memory")
#define CP_WAIT0()    asm volatile("cp.async.wait_group 0;" ::: "memory")
#define CP_WAIT1()    asm volatile("cp.async.wait_group 1;" ::: "memory")
#define ST_SHARED_ZERO16(a) \
    asm volatile("st.shared.v4.b32 [%0], {%1,%1,%1,%1};" :: "r"(a), "r"(0) : "memory")

__device__ __forceinline__ void ldsm_x4(uint32_t a, uint32_t& r0, uint32_t& r1,
                                        uint32_t& r2, uint32_t& r3) {
    asm volatile("ldmatrix.sync.aligned.m8n8.x4.shared.b16 {%0,%1,%2,%3}, [%4];"
                 : "=r"(r0), "=r"(r1), "=r"(r2), "=r"(r3) : "r"(a));
}
__device__ __forceinline__ void ldsm_x4_t(uint32_t a, uint32_t& r0, uint32_t& r1,
                                          uint32_t& r2, uint32_t& r3) {
    asm volatile("ldmatrix.sync.aligned.m8n8.x4.trans.shared.b16 {%0,%1,%2,%3}, [%4];"
                 : "=r"(r0), "=r"(r1), "=r"(r2), "=r"(r3) : "r"(a));
}
__device__ __forceinline__ void mma16816(float* c, const uint32_t* a,
                                         uint32_t b0, uint32_t b1) {
    asm volatile(
        "mma.sync.aligned.m16n8k16.row.col.f32.bf16.bf16.f32 "
        "{%0,%1,%2,%3}, {%4,%5,%6,%7}, {%8,%9}, {%0,%1,%2,%3};"
        : "+f"(c[0]), "+f"(c[1]), "+f"(c[2]), "+f"(c[3])
        : "r"(a[0]), "r"(a[1]), "r"(a[2]), "r"(a[3]), "r"(b0), "r"(b1));
}
__device__ __forceinline__ void mma16816h(float* c, const uint32_t* a,
                                          uint32_t b0, uint32_t b1) {
    asm volatile(
        "mma.sync.aligned.m16n8k16.row.col.f32.f16.f16.f32 "
        "{%0,%1,%2,%3}, {%4,%5,%6,%7}, {%8,%9}, {%0,%1,%2,%3};"
        : "+f"(c[0]), "+f"(c[1]), "+f"(c[2]), "+f"(c[3])
        : "r"(a[0]), "r"(a[1]), "r"(a[2]), "r"(a[3]), "r"(b0), "r"(b1));
}

// ---------------- prep: Q -> fp16 single plane --------------------------------
__global__ __launch_bounds__(256) void qhalf_kernel(const float* __restrict__ Q) {
    size_t i = (size_t)blockIdx.x * 256 + threadIdx.x;   // handles 4 floats
    float4 v = ((const float4*)Q)[i];
    ((__half2*)g_q16)[2 * i]     = __floats2half2_rn(v.x, v.y);
    ((__half2*)g_q16)[2 * i + 1] = __floats2half2_rn(v.z, v.w);
}

// ---------------- prep: W^T + fp16 hi/lo split --------------------------------
__global__ void whalf_kernel(const float* __restrict__ W) {
    __shared__ float t[32][33];
    int bx = blockIdx.x * 32;   // d
    int by = blockIdx.y * 32;   // j
    int tx = threadIdx.x, ty0 = threadIdx.y;
#pragma unroll
    for (int i = 0; i < 4; i++) {
        int ty = ty0 + i * 8;
        t[ty][tx] = W[(size_t)(by + ty) * DIM + bx + tx];
    }
    __syncthreads();
#pragma unroll
    for (int i = 0; i < 4; i++) {
        int ty = ty0 + i * 8;
        float v = t[tx][ty];                     // = W[by+tx][bx+ty]
        __half h = __float2half_rn(v);
        __half l = __float2half_rn(v - __half2float(h));
        size_t o = (size_t)(bx + ty) * DIM + by + tx;   // [d][j]
        g_w16h[o] = h;
        g_w16l[o] = l;
    }
}

// ---------------- prep: keys -> bf16 hi/lo split ------------------------------
__global__ __launch_bounds__(256) void ksplit_kernel(const float* __restrict__ src) {
    size_t i = (size_t)blockIdx.x * 256 + threadIdx.x;
    float4 v = ((const float4*)src)[i];
    __nv_bfloat16 hx = __float2bfloat16(v.x), hy = __float2bfloat16(v.y);
    __nv_bfloat16 hz = __float2bfloat16(v.z), hw = __float2bfloat16(v.w);
    __nv_bfloat16 lx = __float2bfloat16(v.x - __bfloat162float(hx));
    __nv_bfloat16 ly = __float2bfloat16(v.y - __bfloat162float(hy));
    __nv_bfloat16 lz = __float2bfloat16(v.z - __bfloat162float(hz));
    __nv_bfloat16 lw = __float2bfloat16(v.w - __bfloat162float(hw));
    ((__nv_bfloat162*)g_khi)[2 * i]     = __halves2bfloat162(hx, hy);
    ((__nv_bfloat162*)g_khi)[2 * i + 1] = __halves2bfloat162(hz, hw);
    ((__nv_bfloat162*)g_klo)[2 * i]     = __halves2bfloat162(lx, ly);
    ((__nv_bfloat162*)g_klo)[2 * i + 1] = __halves2bfloat162(lz, lw);
}

// ---------------- fp16 2-term GEMM: QT = Q @ W --------------------------------
// CTA 128(m) x 128(n), 8 warps = 2m x 4n, warp tile 64x32. K chunked by 32,
// double-buffered. Per k16: A*Wh + A*Wl (fp32 acc). QT epilogue -> bf16 split.
#define KC    32
#define GSTR  80                  // 64B row + 16B pad
#define GTILE (128 * GSTR)        // 10240
#define OFF_A  0
#define OFF_BH GTILE
#define OFF_BL (2 * GTILE)
#define STG   (3 * GTILE)         // 30720
#define SMEM_G (2 * STG)          // 61440
#define NCHG  (DIM / KC)          // 32

__device__ __forceinline__ void load_stage(uint32_t sst, const __half* a,
                                           const __half* bh, const __half* bl,
                                           int kc0, int tid) {
    // each tile: 128 rows x 32 fp16 (64B) = 4 x 16B segs per row
#pragma unroll
    for (int i = 0; i < 2; i++) {
        int flat = tid + i * 256;            // 0..511
        int r = flat >> 2, seg = flat & 3;
        size_t go = (size_t)r * DIM + kc0 + seg * 8;
        uint32_t so = (uint32_t)(r * GSTR + seg * 16);
        CP_ASYNC16(sst + OFF_A + so, a + go);
        CP_ASYNC16(sst + OFF_BH + so, bh + go);
        CP_ASYNC16(sst + OFF_BL + so, bl + go);
    }
}

__global__ __launch_bounds__(256, 2) void qt_gemm_kernel() {
    extern __shared__ __align__(128) char smem[];
    const int tid  = threadIdx.x;
    const int wid  = tid >> 5, lane = tid & 31;
    const int bn   = blockIdx.x * 128;   // d tile
    const int bm   = blockIdx.y * 128;   // q tile
    const int wm   = (wid >> 2) * 64;
    const int wn   = (wid & 3) * 32;
    const uint32_t sb = smem_u32(smem);

    const __half* qa = g_q16  + (size_t)bm * DIM;
    const __half* wh = g_w16h + (size_t)bn * DIM;
    const __half* wl = g_w16l + (size_t)bn * DIM;

    float acc[4][4][4];
#pragma unroll
    for (int i = 0; i < 4; i++)
#pragma unroll
        for (int j = 0; j < 4; j++)
#pragma unroll
            for (int k = 0; k < 4; k++) acc[i][j][k] = 0.f;

    const uint32_t lmo = (uint32_t)((lane & 15) * GSTR + (lane >> 4) * 16);

    load_stage(sb, qa, wh, wl, 0, tid);
    CP_COMMIT();

    for (int c = 0; c < NCHG; c++) {
        const uint32_t sst = sb + (c & 1) * STG;
        if (c + 1 < NCHG) {
            load_stage(sb + ((c + 1) & 1) * STG, qa, wh, wl, (c + 1) * KC, tid);
            CP_COMMIT();
            CP_WAIT1();
        } else {
            CP_WAIT0();
        }
        __syncthreads();

        const uint32_t aB = sst + OFF_A + wm * GSTR + lmo;
        const uint32_t bH = sst + OFF_BH + wn * GSTR + lmo;
        const uint32_t bL = sst + OFF_BL + wn * GSTR + lmo;

#pragma unroll
        for (int kk = 0; kk < 2; kk++) {
            const uint32_t ko = kk * 32;
            uint32_t af[4][4], bh2[2][4], bl2[2][4];
#pragma unroll
            for (int mi = 0; mi < 4; mi++)
                ldsm_x4(aB + mi * (16 * GSTR) + ko, af[mi][0], af[mi][1], af[mi][2], af[mi][3]);
#pragma unroll
            for (int ni = 0; ni < 2; ni++)
                ldsm_x4(bH + ni * (16 * GSTR) + ko, bh2[ni][0], bh2[ni][1], bh2[ni][2], bh2[ni][3]);
#pragma unroll
            for (int ni = 0; ni < 2; ni++)
                ldsm_x4(bL + ni * (16 * GSTR) + ko, bl2[ni][0], bl2[ni][1], bl2[ni][2], bl2[ni][3]);
#pragma unroll
            for (int mi = 0; mi < 4; mi++)
#pragma unroll
                for (int g = 0; g < 4; g++) {
                    int ni = g >> 1, p = g & 1;
                    mma16816h(acc[mi][g], af[mi], bh2[ni][p], bh2[ni][2 + p]);
                }
#pragma unroll
            for (int mi = 0; mi < 4; mi++)
#pragma unroll
                for (int g = 0; g < 4; g++) {
                    int ni = g >> 1, p = g & 1;
                    mma16816h(acc[mi][g], af[mi], bl2[ni][p], bl2[ni][2 + p]);
                }
        }
        __syncthreads();
    }

    // epilogue: acc -> bf16 hi/lo split
    const int qr = lane >> 2, qc = (lane & 3) * 2;
#pragma unroll
    for (int mi = 0; mi < 4; mi++) {
#pragma unroll
        for (int g = 0; g < 4; g++) {
            const int col = bn + wn + g * 8 + qc;
#pragma unroll
            for (int half = 0; half < 2; half++) {
                const int row = bm + wm + mi * 16 + qr + half * 8;
                float v0 = acc[mi][g][half * 2], v1 = acc[mi][g][half * 2 + 1];
                __nv_bfloat16 h0 = __float2bfloat16(v0);
                __nv_bfloat16 h1 = __float2bfloat16(v1);
                __nv_bfloat16 l0 = __float2bfloat16(v0 - __bfloat162float(h0));
                __nv_bfloat16 l1 = __float2bfloat16(v1 - __bfloat162float(h1));
                size_t o = ((size_t)row * DIM + col) / 2;
                ((__nv_bfloat162*)g_qthi)[o] = __halves2bfloat162(h0, h1);
                ((__nv_bfloat162*)g_qtlo)[o] = __halves2bfloat162(l0, l1);
            }
        }
    }
}

// ---------------- banded attention via mma.sync (validated R4) ----------------
#define QB2    64
#define KSTRB  144
#define PSTRB  240
#define SSTR   132

#define OFF_KH 0u
#define OFF_KL 18432u
#define OFF_QH 36864u
#define OFF_QL 46080u
#define OFF_S  0u
#define OFF_PH 55296u
#define OFF_PL 70656u
#define SMEM_B 86016u

__device__ __forceinline__ void load_ktile(uint32_t sb, int q0, size_t kbase,
                                           int dc, int tid) {
#pragma unroll
    for (int i = 0; i < 4; i++) {
        int flat = tid + i * 256;
        int r = flat >> 3, seg = flat & 7;
        int kr = q0 - WIN + r;
        uint32_t sh = sb + OFF_KH + (uint32_t)(r * KSTRB + seg * 16);
        uint32_t sl = sb + OFF_KL + (uint32_t)(r * KSTRB + seg * 16);
        if ((unsigned)kr < SLEN) {
            size_t go = kbase + (size_t)kr * DIM + dc + seg * 8;
            CP_ASYNC16(sh, g_khi + go);
            CP_ASYNC16(sl, g_klo + go);
        } else {
            ST_SHARED_ZERO16(sh);
            ST_SHARED_ZERO16(sl);
        }
    }
}

__global__ __launch_bounds__(256, 2) void band_attn_kernel(float* __restrict__ out) {
    extern __shared__ __align__(128) char smem[];
    const uint32_t sb = smem_u32(smem);
    const int tid = threadIdx.x, wid = tid >> 5, lane = tid & 31;
    const int b = blockIdx.y, q0 = blockIdx.x * QB2;
    const size_t kbase  = (size_t)b * SLEN * DIM;
    const size_t qtbase = ((size_t)b * SLEN + q0) * DIM;

    const int wm  = (wid >> 1) * 16;
    const int wn  = (wid & 1) * 64;
    const int wn3 = (wid & 1) * 32;

    float acc[8][4];
#pragma unroll
    for (int i = 0; i < 8; i++)
#pragma unroll
        for (int j = 0; j < 4; j++) acc[i][j] = 0.f;

    const uint32_t lmoA = (uint32_t)((wm + (lane & 15)) * KSTRB + (lane >> 4) * 16);
    const uint32_t lmoB = (uint32_t)((lane & 15) * KSTRB + (lane >> 4) * 16);

    for (int ch = 0; ch < 16; ch++) {
        const int dc = ch * 64;
#pragma unroll
        for (int i = 0; i < 2; i++) {
            int flat = tid + i * 256;
            int r = flat >> 3, seg = flat & 7;
            size_t go = qtbase + (size_t)r * DIM + dc + seg * 8;
            uint32_t so = (uint32_t)(r * KSTRB + seg * 16);
            CP_ASYNC16(sb + OFF_QH + so, g_qthi + go);
            CP_ASYNC16(sb + OFF_QL + so, g_qtlo + go);
        }
        load_ktile(sb, q0, kbase, dc, tid);
        CP_COMMIT();
        CP_WAIT0();
        __syncthreads();

#pragma unroll
        for (int ks = 0; ks < 4; ks++) {
            const uint32_t ko = ks * 32;
            uint32_t ah[4], al[4], bh[4][4], bl[4][4];
            ldsm_x4(sb + OFF_QH + lmoA + ko, ah[0], ah[1], ah[2], ah[3]);
            ldsm_x4(sb + OFF_QL + lmoA + ko, al[0], al[1], al[2], al[3]);
#pragma unroll
            for (int g = 0; g < 4; g++) {
                uint32_t ba = (uint32_t)((wn + g * 16) * KSTRB) + lmoB + ko;
                ldsm_x4(sb + OFF_KH + ba, bh[g][0], bh[g][1], bh[g][2], bh[g][3]);
                ldsm_x4(sb + OFF_KL + ba, bl[g][0], bl[g][1], bl[g][2], bl[g][3]);
            }
#pragma unroll
            for (int nf = 0; nf < 8; nf++) {
                int g = nf >> 1, p = nf & 1;
                mma16816(acc[nf], ah, bh[g][p], bh[g][2 + p]);
            }
#pragma unroll
            for (int nf = 0; nf < 8; nf++) {
                int g = nf >> 1, p = nf & 1;
                mma16816(acc[nf], ah, bl[g][p], bl[g][2 + p]);
            }
#pragma unroll
            for (int nf = 0; nf < 8; nf++) {
                int g = nf >> 1, p = nf & 1;
                mma16816(acc[nf], al, bh[g][p], bh[g][2 + p]);
            }
        }
        __syncthreads();
    }

    {
        float* S = (float*)(smem + OFF_S);
        int r0 = wm + (lane >> 2);
        int c0 = wn + (lane & 3) * 2;
#pragma unroll
        for (int nf = 0; nf < 8; nf++) {
            int c = c0 + nf * 8;
            *(float2*)&S[r0 * SSTR + c]       = make_float2(acc[nf][0], acc[nf][1]);
            *(float2*)&S[(r0 + 8) * SSTR + c] = make_float2(acc[nf][2], acc[nf][3]);
        }
    }
    __syncthreads();

    {
        float* S = (float*)(smem + OFF_S);
        __nv_bfloat16* PH = (__nv_bfloat16*)(smem + OFF_PH);
        __nv_bfloat16* PL = (__nv_bfloat16*)(smem + OFF_PL);
        const int row = tid >> 2, part = tid & 3;
        int rmin = row;
        int t = WIN - q0;
        if (t > rmin) rmin = t;
        int rmax = row + 2 * WIN;
        t = (SLEN - 1) + WIN - q0;
        if (t < rmax) rmax = t;
        const int cbeg = part * 32, cend = cbeg + 32;

        float mx = -3.4e38f;
        for (int c = cbeg; c < cend; c++)
            if (c >= rmin && c <= rmax) mx = fmaxf(mx, S[row * SSTR + c]);
        mx = fmaxf(mx, __shfl_xor_sync(0xFFFFFFFFu, mx, 1));
        mx = fmaxf(mx, __shfl_xor_sync(0xFFFFFFFFu, mx, 2));

        float sum = 0.f;
        for (int c = cbeg; c < cend; c++) {
            float e = (c >= rmin && c <= rmax) ? __expf(S[row * SSTR + c] - mx) : 0.f;
            S[row * SSTR + c] = e;
            sum += e;
        }
        sum += __shfl_xor_sync(0xFFFFFFFFu, sum, 1);
        sum += __shfl_xor_sync(0xFFFFFFFFu, sum, 2);
        const float inv = 1.f / sum;

        for (int c = cbeg; c < cend && c < 112; c++) {
            float p = S[row * SSTR + c] * inv;
            __nv_bfloat16 h = __float2bfloat16(p);
            __nv_bfloat16 l = __float2bfloat16(p - __bfloat162float(h));
            PH[row * 120 + c] = h;
            PL[row * 120 + c] = l;
        }
    }
    __syncthreads();

    const uint32_t lmoP = (uint32_t)((wm + (lane & 15)) * PSTRB + (lane >> 4) * 16);
    for (int ch = 0; ch < 16; ch++) {
        const int dc = ch * 64;
        load_ktile(sb, q0, kbase, dc, tid);
        CP_COMMIT();
        CP_WAIT0();
        __syncthreads();

        float oacc[4][4];
#pragma unroll
        for (int i = 0; i < 4; i++)
#pragma unroll
            for (int j = 0; j < 4; j++) oacc[i][j] = 0.f;

#pragma unroll
        for (int ks = 0; ks < 7; ks++) {
            uint32_t ah[4], al[4], bh[2][4], bl[2][4];
            ldsm_x4(sb + OFF_PH + lmoP + ks * 32, ah[0], ah[1], ah[2], ah[3]);
            ldsm_x4(sb + OFF_PL + lmoP + ks * 32, al[0], al[1], al[2], al[3]);
#pragma unroll
            for (int g = 0; g < 2; g++) {
                uint32_t ba = (uint32_t)((ks * 16 + (lane & 15)) * KSTRB +
                                         wn3 * 2 + g * 32 + (lane >> 4) * 16);
                ldsm_x4_t(sb + OFF_KH + ba, bh[g][0], bh[g][1], bh[g][2], bh[g][3]);
                ldsm_x4_t(sb + OFF_KL + ba, bl[g][0], bl[g][1], bl[g][2], bl[g][3]);
            }
#pragma unroll
            for (int nf = 0; nf < 4; nf++) {
                int g = nf >> 1, p = nf & 1;
                mma16816(oacc[nf], ah, bh[g][2 * p], bh[g][2 * p + 1]);
            }
#pragma unroll
            for (int nf = 0; nf < 4; nf++) {
                int g = nf >> 1, p = nf & 1;
                mma16816(oacc[nf], ah, bl[g][2 * p], bl[g][2 * p + 1]);
            }
#pragma unroll
            for (int nf = 0; nf < 4; nf++) {
                int g = nf >> 1, p = nf & 1;
                mma16816(oacc[nf], al, bh[g][2 * p], bh[g][2 * p + 1]);
            }
        }

        const int r0 = q0 + wm + (lane >> 2);
        const int c0 = dc + wn3 + (lane & 3) * 2;
#pragma unroll
        for (int nf = 0; nf < 4; nf++) {
            int c = c0 + nf * 8;
            *(float2*)(out + kbase + (size_t)r0 * DIM + c) =
                make_float2(oacc[nf][0], oacc[nf][1]);
            *(float2*)(out + kbase + (size_t)(r0 + 8) * DIM + c) =
                make_float2(oacc[nf][2], oacc[nf][3]);
        }
        __syncthreads();
    }
}

extern "C" void kernel_launch(void* const* d_in, const int* in_sizes, int n_in,
                              void* d_out, int out_size) {
    const float* queries = (const float*)d_in[0];
    const float* keys    = (const float*)d_in[1];
    const float* W       = (const float*)d_in[2];
    // d_in[3] = b_reduce: per-(b,q) constant added to all logits -> softmax-invariant, unused.
    float* out = (float*)d_out;

    cudaFuncSetAttribute(qt_gemm_kernel, cudaFuncAttributeMaxDynamicSharedMemorySize, SMEM_G);
    cudaFuncSetAttribute(band_attn_kernel, cudaFuncAttributeMaxDynamicSharedMemorySize, SMEM_B);

    const int elemGrid = (MTOT * DIM) / 4 / 256;
    qhalf_kernel<<<elemGrid, 256>>>(queries);
    ksplit_kernel<<<elemGrid, 256>>>(keys);
    whalf_kernel<<<dim3(DIM / 32, DIM / 32), dim3(32, 8)>>>(W);

    dim3 gg(DIM / 128, MTOT / 128);
    qt_gemm_kernel<<<gg, 256, SMEM_G>>>();

    dim3 g2(SLEN / QB2, BATCH);
    band_attn_kernel<<<g2, 256, SMEM_B>>>(out);
}

// round 8
// speedup vs baseline: 2.5144x; 1.0723x over previous
#include <cuda_runtime.h>
#include <cuda_bf16.h>
#include <cuda_fp16.h>
#include <cstdint>

#define BATCH 8
#define SLEN  2048
#define DIM   1024
#define WIN   20
#define MTOT  (BATCH * SLEN)   // 16384

// ---------------- static device scratch -------------------------------------
__device__ __half        g_q16 [(size_t)MTOT * DIM];  // Q fp16 (single plane)
__device__ __half        g_w16h[(size_t)DIM * DIM];   // W^T fp16 hi: [d][j]
__device__ __half        g_w16l[(size_t)DIM * DIM];   // W^T fp16 residual
__device__ __nv_bfloat16 g_qthi[(size_t)MTOT * DIM];  // QT = Q@W, bf16 split
__device__ __nv_bfloat16 g_qtlo[(size_t)MTOT * DIM];
__device__ __nv_bfloat16 g_khi [(size_t)MTOT * DIM];  // keys bf16 split
__device__ __nv_bfloat16 g_klo [(size_t)MTOT * DIM];

// ---------------- helpers ----------------------------------------------------
__device__ __forceinline__ uint32_t smem_u32(const void* p) {
    uint32_t a;
    asm("{ .reg .u64 t; cvta.to.shared.u64 t, %1; cvt.u32.u64 %0, t; }" : "=r"(a) : "l"(p));
    return a;
}
#define CP_ASYNC16(sd, gp) \
    asm volatile("cp.async.cg.shared.global [%0], [%1], 16;" :: "r"(sd), "l"(gp) : "memory")
#define CP_COMMIT()   asm volatile("cp.async.commit_group;" ::: "memory")
#define CP_WAIT0()    asm volatile("cp.async.wait_group 0;" ::: "memory")
#define CP_WAIT1()    asm volatile("cp.async.wait_group 1;" ::: "memory")
#define ST_SHARED_ZERO16(a) \
    asm volatile("st.shared.v4.b32 [%0], {%1,%1,%1,%1};" :: "r"(a), "r"(0) : "memory")

__device__ __forceinline__ void ldsm_x4(uint32_t a, uint32_t& r0, uint32_t& r1,
                                        uint32_t& r2, uint32_t& r3) {
    asm volatile("ldmatrix.sync.aligned.m8n8.x4.shared.b16 {%0,%1,%2,%3}, [%4];"
                 : "=r"(r0), "=r"(r1), "=r"(r2), "=r"(r3) : "r"(a));
}
__device__ __forceinline__ void ldsm_x4_t(uint32_t a, uint32_t& r0, uint32_t& r1,
                                          uint32_t& r2, uint32_t& r3) {
    asm volatile("ldmatrix.sync.aligned.m8n8.x4.trans.shared.b16 {%0,%1,%2,%3}, [%4];"
                 : "=r"(r0), "=r"(r1), "=r"(r2), "=r"(r3) : "r"(a));
}
__device__ __forceinline__ void mma16816(float* c, const uint32_t* a,
                                         uint32_t b0, uint32_t b1) {
    asm volatile(
        "mma.sync.aligned.m16n8k16.row.col.f32.bf16.bf16.f32 "
        "{%0,%1,%2,%3}, {%4,%5,%6,%7}, {%8,%9}, {%0,%1,%2,%3};"
        : "+f"(c[0]), "+f"(c[1]), "+f"(c[2]), "+f"(c[3])
        : "r"(a[0]), "r"(a[1]), "r"(a[2]), "r"(a[3]), "r"(b0), "r"(b1));
}
__device__ __forceinline__ void mma16816h(float* c, const uint32_t* a,
                                          uint32_t b0, uint32_t b1) {
    asm volatile(
        "mma.sync.aligned.m16n8k16.row.col.f32.f16.f16.f32 "
        "{%0,%1,%2,%3}, {%4,%5,%6,%7}, {%8,%9}, {%0,%1,%2,%3};"
        : "+f"(c[0]), "+f"(c[1]), "+f"(c[2]), "+f"(c[3])
        : "r"(a[0]), "r"(a[1]), "r"(a[2]), "r"(a[3]), "r"(b0), "r"(b1));
}

// ---------------- prep: Q -> fp16 single plane --------------------------------
__global__ __launch_bounds__(256) void qhalf_kernel(const float* __restrict__ Q) {
    size_t i = (size_t)blockIdx.x * 256 + threadIdx.x;   // handles 4 floats
    float4 v = ((const float4*)Q)[i];
    ((__half2*)g_q16)[2 * i]     = __floats2half2_rn(v.x, v.y);
    ((__half2*)g_q16)[2 * i + 1] = __floats2half2_rn(v.z, v.w);
}

// ---------------- prep: W^T + fp16 hi/lo split --------------------------------
__global__ void whalf_kernel(const float* __restrict__ W) {
    __shared__ float t[32][33];
    int bx = blockIdx.x * 32;   // d
    int by = blockIdx.y * 32;   // j
    int tx = threadIdx.x, ty0 = threadIdx.y;
#pragma unroll
    for (int i = 0; i < 4; i++) {
        int ty = ty0 + i * 8;
        t[ty][tx] = W[(size_t)(by + ty) * DIM + bx + tx];
    }
    __syncthreads();
#pragma unroll
    for (int i = 0; i < 4; i++) {
        int ty = ty0 + i * 8;
        float v = t[tx][ty];                     // = W[by+tx][bx+ty]
        __half h = __float2half_rn(v);
        __half l = __float2half_rn(v - __half2float(h));
        size_t o = (size_t)(bx + ty) * DIM + by + tx;   // [d][j]
        g_w16h[o] = h;
        g_w16l[o] = l;
    }
}

// ---------------- prep: keys -> bf16 hi/lo split ------------------------------
__global__ __launch_bounds__(256) void ksplit_kernel(const float* __restrict__ src) {
    size_t i = (size_t)blockIdx.x * 256 + threadIdx.x;
    float4 v = ((const float4*)src)[i];
    __nv_bfloat16 hx = __float2bfloat16(v.x), hy = __float2bfloat16(v.y);
    __nv_bfloat16 hz = __float2bfloat16(v.z), hw = __float2bfloat16(v.w);
    __nv_bfloat16 lx = __float2bfloat16(v.x - __bfloat162float(hx));
    __nv_bfloat16 ly = __float2bfloat16(v.y - __bfloat162float(hy));
    __nv_bfloat16 lz = __float2bfloat16(v.z - __bfloat162float(hz));
    __nv_bfloat16 lw = __float2bfloat16(v.w - __bfloat162float(hw));
    ((__nv_bfloat162*)g_khi)[2 * i]     = __halves2bfloat162(hx, hy);
    ((__nv_bfloat162*)g_khi)[2 * i + 1] = __halves2bfloat162(hz, hw);
    ((__nv_bfloat162*)g_klo)[2 * i]     = __halves2bfloat162(lx, ly);
    ((__nv_bfloat162*)g_klo)[2 * i + 1] = __halves2bfloat162(lz, lw);
}

// ---------------- fp16 2-term GEMM: QT = Q @ W  (validated R6) ----------------
#define KC    32
#define GSTR  80
#define GTILE (128 * GSTR)
#define OFF_A  0
#define OFF_BH GTILE
#define OFF_BL (2 * GTILE)
#define STG   (3 * GTILE)
#define SMEM_G (2 * STG)
#define NCHG  (DIM / KC)

__device__ __forceinline__ void load_stage(uint32_t sst, const __half* a,
                                           const __half* bh, const __half* bl,
                                           int kc0, int tid) {
#pragma unroll
    for (int i = 0; i < 2; i++) {
        int flat = tid + i * 256;
        int r = flat >> 2, seg = flat & 3;
        size_t go = (size_t)r * DIM + kc0 + seg * 8;
        uint32_t so = (uint32_t)(r * GSTR + seg * 16);
        CP_ASYNC16(sst + OFF_A + so, a + go);
        CP_ASYNC16(sst + OFF_BH + so, bh + go);
        CP_ASYNC16(sst + OFF_BL + so, bl + go);
    }
}

__global__ __launch_bounds__(256, 2) void qt_gemm_kernel() {
    extern __shared__ __align__(128) char smem[];
    const int tid  = threadIdx.x;
    const int wid  = tid >> 5, lane = tid & 31;
    const int bn   = blockIdx.x * 128;
    const int bm   = blockIdx.y * 128;
    const int wm   = (wid >> 2) * 64;
    const int wn   = (wid & 3) * 32;
    const uint32_t sb = smem_u32(smem);

    const __half* qa = g_q16  + (size_t)bm * DIM;
    const __half* wh = g_w16h + (size_t)bn * DIM;
    const __half* wl = g_w16l + (size_t)bn * DIM;

    float acc[4][4][4];
#pragma unroll
    for (int i = 0; i < 4; i++)
#pragma unroll
        for (int j = 0; j < 4; j++)
#pragma unroll
            for (int k = 0; k < 4; k++) acc[i][j][k] = 0.f;

    const uint32_t lmo = (uint32_t)((lane & 15) * GSTR + (lane >> 4) * 16);

    load_stage(sb, qa, wh, wl, 0, tid);
    CP_COMMIT();

    for (int c = 0; c < NCHG; c++) {
        const uint32_t sst = sb + (c & 1) * STG;
        if (c + 1 < NCHG) {
            load_stage(sb + ((c + 1) & 1) * STG, qa, wh, wl, (c + 1) * KC, tid);
            CP_COMMIT();
            CP_WAIT1();
        } else {
            CP_WAIT0();
        }
        __syncthreads();

        const uint32_t aB = sst + OFF_A + wm * GSTR + lmo;
        const uint32_t bH = sst + OFF_BH + wn * GSTR + lmo;
        const uint32_t bL = sst + OFF_BL + wn * GSTR + lmo;

#pragma unroll
        for (int kk = 0; kk < 2; kk++) {
            const uint32_t ko = kk * 32;
            uint32_t af[4][4], bh2[2][4], bl2[2][4];
#pragma unroll
            for (int mi = 0; mi < 4; mi++)
                ldsm_x4(aB + mi * (16 * GSTR) + ko, af[mi][0], af[mi][1], af[mi][2], af[mi][3]);
#pragma unroll
            for (int ni = 0; ni < 2; ni++)
                ldsm_x4(bH + ni * (16 * GSTR) + ko, bh2[ni][0], bh2[ni][1], bh2[ni][2], bh2[ni][3]);
#pragma unroll
            for (int ni = 0; ni < 2; ni++)
                ldsm_x4(bL + ni * (16 * GSTR) + ko, bl2[ni][0], bl2[ni][1], bl2[ni][2], bl2[ni][3]);
#pragma unroll
            for (int mi = 0; mi < 4; mi++)
#pragma unroll
                for (int g = 0; g < 4; g++) {
                    int ni = g >> 1, p = g & 1;
                    mma16816h(acc[mi][g], af[mi], bh2[ni][p], bh2[ni][2 + p]);
                }
#pragma unroll
            for (int mi = 0; mi < 4; mi++)
#pragma unroll
                for (int g = 0; g < 4; g++) {
                    int ni = g >> 1, p = g & 1;
                    mma16816h(acc[mi][g], af[mi], bl2[ni][p], bl2[ni][2 + p]);
                }
        }
        __syncthreads();
    }

    const int qr = lane >> 2, qc = (lane & 3) * 2;
#pragma unroll
    for (int mi = 0; mi < 4; mi++) {
#pragma unroll
        for (int g = 0; g < 4; g++) {
            const int col = bn + wn + g * 8 + qc;
#pragma unroll
            for (int half = 0; half < 2; half++) {
                const int row = bm + wm + mi * 16 + qr + half * 8;
                float v0 = acc[mi][g][half * 2], v1 = acc[mi][g][half * 2 + 1];
                __nv_bfloat16 h0 = __float2bfloat16(v0);
                __nv_bfloat16 h1 = __float2bfloat16(v1);
                __nv_bfloat16 l0 = __float2bfloat16(v0 - __bfloat162float(h0));
                __nv_bfloat16 l1 = __float2bfloat16(v1 - __bfloat162float(h1));
                size_t o = ((size_t)row * DIM + col) / 2;
                ((__nv_bfloat162*)g_qthi)[o] = __halves2bfloat162(h0, h1);
                ((__nv_bfloat162*)g_qtlo)[o] = __halves2bfloat162(l0, l1);
            }
        }
    }
}

// ---------------- windowed banded attention ----------------------------------
// CTA: 64 queries (one batch) = 4 groups of 16. Group g owns a 64-key window
// starting at q0+16g-24 (band cols [rm+4, rm+44] fit in [4,59]).
// K tile rows [q0-24, q0+87] = 112 rows. Warp w -> group w>>1, half w&1.
#define QB3  64
#define KS3  144           // bytes per 64-elem row (+16B pad)
#define SS3  68            // S row stride (floats)
#define PS3  72            // P row stride (bf16 elems) = 144 B

#define O3_KH 0u
#define O3_KL 16128u       // 112*144
#define O3_QH 32256u
#define O3_QL 41472u       // +64*144
#define O3_S  0u           // overlays K (dead when S materialized)
#define O3_PH 32256u       // overlays QT (dead after phase 1)
#define O3_PL 41472u
#define SMEM_B3 50688u

__device__ __forceinline__ void load_k3(uint32_t sb, int q0, size_t kbase,
                                        int dc, int tid) {
    // 112 rows x 8 segs (16B) per plane = 896 flats
#pragma unroll
    for (int i = 0; i < 4; i++) {
        int flat = tid + i * 256;
        if (flat < 896) {
            int r = flat >> 3, seg = flat & 7;
            int kr = q0 - 24 + r;
            uint32_t sh = sb + O3_KH + (uint32_t)(r * KS3 + seg * 16);
            uint32_t sl = sb + O3_KL + (uint32_t)(r * KS3 + seg * 16);
            if ((unsigned)kr < SLEN) {
                size_t go = kbase + (size_t)kr * DIM + dc + seg * 8;
                CP_ASYNC16(sh, g_khi + go);
                CP_ASYNC16(sl, g_klo + go);
            } else {
                ST_SHARED_ZERO16(sh);
                ST_SHARED_ZERO16(sl);
            }
        }
    }
}

__global__ __launch_bounds__(256, 2) void band_attn_kernel(float* __restrict__ out) {
    extern __shared__ __align__(128) char smem[];
    const uint32_t sb = smem_u32(smem);
    const int tid = threadIdx.x, wid = tid >> 5, lane = tid & 31;
    const int b = blockIdx.y, q0 = blockIdx.x * QB3;
    const size_t kbase  = (size_t)b * SLEN * DIM;
    const size_t qtbase = ((size_t)b * SLEN + q0) * DIM;

    const int g  = wid >> 1;      // query group 0..3
    const int hw = wid & 1;       // half (S: window cols; AV: d cols)

    // ---------------- phase 1: S (16x64 per group, 3-term bf16) -------------
    float sacc[4][4];
#pragma unroll
    for (int i = 0; i < 4; i++)
#pragma unroll
        for (int j = 0; j < 4; j++) sacc[i][j] = 0.f;

    const uint32_t lmA = (uint32_t)((16 * g + (lane & 15)) * KS3 + (lane >> 4) * 16);
    const uint32_t lmB = (uint32_t)((16 * g + 32 * hw + (lane & 15)) * KS3 + (lane >> 4) * 16);

    for (int ch = 0; ch < 16; ch++) {
        const int dc = ch * 64;
        // QT tiles: 64 rows x 8 segs per plane = 512 flats
#pragma unroll
        for (int i = 0; i < 2; i++) {
            int flat = tid + i * 256;
            int r = flat >> 3, seg = flat & 7;
            size_t go = qtbase + (size_t)r * DIM + dc + seg * 8;
            uint32_t so = (uint32_t)(r * KS3 + seg * 16);
            CP_ASYNC16(sb + O3_QH + so, g_qthi + go);
            CP_ASYNC16(sb + O3_QL + so, g_qtlo + go);
        }
        load_k3(sb, q0, kbase, dc, tid);
        CP_COMMIT();
        CP_WAIT0();
        __syncthreads();

#pragma unroll
        for (int ks = 0; ks < 4; ks++) {
            const uint32_t ko = ks * 32;
            uint32_t ah[4], al[4], bh[2][4], bl[2][4];
            ldsm_x4(sb + O3_QH + lmA + ko, ah[0], ah[1], ah[2], ah[3]);
            ldsm_x4(sb + O3_QL + lmA + ko, al[0], al[1], al[2], al[3]);
#pragma unroll
            for (int nb = 0; nb < 2; nb++) {
                uint32_t ba = lmB + (uint32_t)(nb * 16 * KS3) + ko;
                ldsm_x4(sb + O3_KH + ba, bh[nb][0], bh[nb][1], bh[nb][2], bh[nb][3]);
                ldsm_x4(sb + O3_KL + ba, bl[nb][0], bl[nb][1], bl[nb][2], bl[nb][3]);
            }
#pragma unroll
            for (int nf = 0; nf < 4; nf++) {
                int nb = nf >> 1, p = nf & 1;
                mma16816(sacc[nf], ah, bh[nb][p], bh[nb][2 + p]);
            }
#pragma unroll
            for (int nf = 0; nf < 4; nf++) {
                int nb = nf >> 1, p = nf & 1;
                mma16816(sacc[nf], ah, bl[nb][p], bl[nb][2 + p]);
            }
#pragma unroll
            for (int nf = 0; nf < 4; nf++) {
                int nb = nf >> 1, p = nf & 1;
                mma16816(sacc[nf], al, bh[nb][p], bh[nb][2 + p]);
            }
        }
        __syncthreads();
    }

    // ---------------- S frags -> smem ---------------------------------------
    {
        float* S = (float*)(smem + O3_S);
        int r0 = 16 * g + (lane >> 2);
        int c0 = 32 * hw + (lane & 3) * 2;
#pragma unroll
        for (int nf = 0; nf < 4; nf++) {
            int c = c0 + nf * 8;
            *(float2*)&S[r0 * SS3 + c]       = make_float2(sacc[nf][0], sacc[nf][1]);
            *(float2*)&S[(r0 + 8) * SS3 + c] = make_float2(sacc[nf][2], sacc[nf][3]);
        }
    }
    __syncthreads();

    // ---------------- softmax over each row's 64-col window ------------------
    if (tid < 128) {
        float* S = (float*)(smem + O3_S);
        __nv_bfloat16* PH = (__nv_bfloat16*)(smem + O3_PH);
        __nv_bfloat16* PL = (__nv_bfloat16*)(smem + O3_PL);
        const int row = tid >> 1, half = tid & 1;
        const int rm = row & 15;
        const int w0 = q0 + (row & ~15) - 24;     // window start (global key)
        int cmin = rm + 4;
        { int t = -w0;            if (t > cmin) cmin = t; }
        int cmax = rm + 44;
        { int t = SLEN - 1 - w0;  if (t < cmax) cmax = t; }
        const int cbeg = half * 32, cend = cbeg + 32;

        float mx = -3.4e38f;
        for (int c = cbeg; c < cend; c++)
            if (c >= cmin && c <= cmax) mx = fmaxf(mx, S[row * SS3 + c]);
        mx = fmaxf(mx, __shfl_xor_sync(0xFFFFFFFFu, mx, 1));

        float sum = 0.f;
        for (int c = cbeg; c < cend; c++) {
            float e = (c >= cmin && c <= cmax) ? __expf(S[row * SS3 + c] - mx) : 0.f;
            S[row * SS3 + c] = e;
            sum += e;
        }
        sum += __shfl_xor_sync(0xFFFFFFFFu, sum, 1);
        const float inv = 1.f / sum;

        for (int c = cbeg; c < cend; c++) {
            float p = S[row * SS3 + c] * inv;
            __nv_bfloat16 h = __float2bfloat16(p);
            __nv_bfloat16 l = __float2bfloat16(p - __bfloat162float(h));
            PH[row * PS3 + c] = h;
            PL[row * PS3 + c] = l;
        }
    }
    __syncthreads();

    // ---------------- phase 3: O = P . K over 64-key windows -----------------
    const uint32_t lmP = (uint32_t)((16 * g + (lane & 15)) * KS3 + (lane >> 4) * 16);
    for (int ch = 0; ch < 16; ch++) {
        const int dc = ch * 64;
        load_k3(sb, q0, kbase, dc, tid);
        CP_COMMIT();
        CP_WAIT0();
        __syncthreads();

        float oacc[4][4];
#pragma unroll
        for (int i = 0; i < 4; i++)
#pragma unroll
            for (int j = 0; j < 4; j++) oacc[i][j] = 0.f;

#pragma unroll
        for (int ks = 0; ks < 4; ks++) {
            const uint32_t ko = ks * 32;
            uint32_t ah[4], al[4], bh[2][4], bl[2][4];
            ldsm_x4(sb + O3_PH + lmP + ko, ah[0], ah[1], ah[2], ah[3]);
            ldsm_x4(sb + O3_PL + lmP + ko, al[0], al[1], al[2], al[3]);
#pragma unroll
            for (int ds = 0; ds < 2; ds++) {
                uint32_t ba = (uint32_t)((16 * g + ks * 16 + (lane & 15)) * KS3 +
                                         64 * hw + ds * 32 + (lane >> 4) * 16);
                ldsm_x4_t(sb + O3_KH + ba, bh[ds][0], bh[ds][1], bh[ds][2], bh[ds][3]);
                ldsm_x4_t(sb + O3_KL + ba, bl[ds][0], bl[ds][1], bl[ds][2], bl[ds][3]);
            }
#pragma unroll
            for (int nf = 0; nf < 4; nf++) {
                int ds = nf >> 1, p = nf & 1;
                mma16816(oacc[nf], ah, bh[ds][2 * p], bh[ds][2 * p + 1]);
            }
#pragma unroll
            for (int nf = 0; nf < 4; nf++) {
                int ds = nf >> 1, p = nf & 1;
                mma16816(oacc[nf], ah, bl[ds][2 * p], bl[ds][2 * p + 1]);
            }
#pragma unroll
            for (int nf = 0; nf < 4; nf++) {
                int ds = nf >> 1, p = nf & 1;
                mma16816(oacc[nf], al, bh[ds][2 * p], bh[ds][2 * p + 1]);
            }
        }

        const int r0 = q0 + 16 * g + (lane >> 2);
        const int c0 = dc + 32 * hw + (lane & 3) * 2;
#pragma unroll
        for (int nf = 0; nf < 4; nf++) {
            int c = c0 + nf * 8;
            *(float2*)(out + kbase + (size_t)r0 * DIM + c) =
                make_float2(oacc[nf][0], oacc[nf][1]);
            *(float2*)(out + kbase + (size_t)(r0 + 8) * DIM + c) =
                make_float2(oacc[nf][2], oacc[nf][3]);
        }
        __syncthreads();
    }
}

extern "C" void kernel_launch(void* const* d_in, const int* in_sizes, int n_in,
                              void* d_out, int out_size) {
    const float* queries = (const float*)d_in[0];
    const float* keys    = (const float*)d_in[1];
    const float* W       = (const float*)d_in[2];
    // d_in[3] = b_reduce: per-(b,q) constant added to all logits -> softmax-invariant, unused.
    float* out = (float*)d_out;

    cudaFuncSetAttribute(qt_gemm_kernel, cudaFuncAttributeMaxDynamicSharedMemorySize, SMEM_G);
    cudaFuncSetAttribute(band_attn_kernel, cudaFuncAttributeMaxDynamicSharedMemorySize, SMEM_B3);

    const int elemGrid = (MTOT * DIM) / 4 / 256;
    qhalf_kernel<<<elemGrid, 256>>>(queries);
    ksplit_kernel<<<elemGrid, 256>>>(keys);
    whalf_kernel<<<dim3(DIM / 32, DIM / 32), dim3(32, 8)>>>(W);

    dim3 gg(DIM / 128, MTOT / 128);
    qt_gemm_kernel<<<gg, 256, SMEM_G>>>();

    dim3 g2(SLEN / QB3, BATCH);
    band_attn_kernel<<<g2, 256, SMEM_B3>>>(out);
}

// round 9
// speedup vs baseline: 2.5452x; 1.0123x over previous
#include <cuda_runtime.h>
#include <cuda_bf16.h>
#include <cuda_fp16.h>
#include <cstdint>

#define BATCH 8
#define SLEN  2048
#define DIM   1024
#define WIN   20
#define MTOT  (BATCH * SLEN)   // 16384

// ---------------- static device scratch -------------------------------------
__device__ __half        g_q16 [(size_t)MTOT * DIM];  // Q fp16 (single plane)
__device__ __half        g_w16h[(size_t)DIM * DIM];   // W^T fp16 hi: [d][j]
__device__ __half        g_w16l[(size_t)DIM * DIM];   // W^T fp16 residual
__device__ __nv_bfloat16 g_qthi[(size_t)MTOT * DIM];  // QT = Q@W, bf16 split
__device__ __nv_bfloat16 g_qtlo[(size_t)MTOT * DIM];
__device__ __nv_bfloat16 g_khi [(size_t)MTOT * DIM];  // keys bf16 split
__device__ __nv_bfloat16 g_klo [(size_t)MTOT * DIM];

// ---------------- helpers ----------------------------------------------------
__device__ __forceinline__ uint32_t smem_u32(const void* p) {
    uint32_t a;
    asm("{ .reg .u64 t; cvta.to.shared.u64 t, %1; cvt.u32.u64 %0, t; }" : "=r"(a) : "l"(p));
    return a;
}
#define CP_ASYNC16(sd, gp) \
    asm volatile("cp.async.cg.shared.global [%0], [%1], 16;" :: "r"(sd), "l"(gp) : "memory")
#define CP_COMMIT()   asm volatile("cp.async.commit_group;" ::: "memory")
#define CP_WAIT0()    asm volatile("cp.async.wait_group 0;" ::: "memory")
#define CP_WAIT1()    asm volatile("cp.async.wait_group 1;" ::: "memory")
#define ST_SHARED_ZERO16(a) \
    asm volatile("st.shared.v4.b32 [%0], {%1,%1,%1,%1};" :: "r"(a), "r"(0) : "memory")

__device__ __forceinline__ void ldsm_x4(uint32_t a, uint32_t& r0, uint32_t& r1,
                                        uint32_t& r2, uint32_t& r3) {
    asm volatile("ldmatrix.sync.aligned.m8n8.x4.shared.b16 {%0,%1,%2,%3}, [%4];"
                 : "=r"(r0), "=r"(r1), "=r"(r2), "=r"(r3) : "r"(a));
}
__device__ __forceinline__ void ldsm_x4_t(uint32_t a, uint32_t& r0, uint32_t& r1,
                                          uint32_t& r2, uint32_t& r3) {
    asm volatile("ldmatrix.sync.aligned.m8n8.x4.trans.shared.b16 {%0,%1,%2,%3}, [%4];"
                 : "=r"(r0), "=r"(r1), "=r"(r2), "=r"(r3) : "r"(a));
}
__device__ __forceinline__ void mma16816(float* c, const uint32_t* a,
                                         uint32_t b0, uint32_t b1) {
    asm volatile(
        "mma.sync.aligned.m16n8k16.row.col.f32.bf16.bf16.f32 "
        "{%0,%1,%2,%3}, {%4,%5,%6,%7}, {%8,%9}, {%0,%1,%2,%3};"
        : "+f"(c[0]), "+f"(c[1]), "+f"(c[2]), "+f"(c[3])
        : "r"(a[0]), "r"(a[1]), "r"(a[2]), "r"(a[3]), "r"(b0), "r"(b1));
}
__device__ __forceinline__ void mma16816h(float* c, const uint32_t* a,
                                          uint32_t b0, uint32_t b1) {
    asm volatile(
        "mma.sync.aligned.m16n8k16.row.col.f32.f16.f16.f32 "
        "{%0,%1,%2,%3}, {%4,%5,%6,%7}, {%8,%9}, {%0,%1,%2,%3};"
        : "+f"(c[0]), "+f"(c[1]), "+f"(c[2]), "+f"(c[3])
        : "r"(a[0]), "r"(a[1]), "r"(a[2]), "r"(a[3]), "r"(b0), "r"(b1));
}

// ---------------- prep: Q -> fp16 single plane --------------------------------
__global__ __launch_bounds__(256) void qhalf_kernel(const float* __restrict__ Q) {
    size_t i = (size_t)blockIdx.x * 256 + threadIdx.x;   // handles 4 floats
    float4 v = ((const float4*)Q)[i];
    ((__half2*)g_q16)[2 * i]     = __floats2half2_rn(v.x, v.y);
    ((__half2*)g_q16)[2 * i + 1] = __floats2half2_rn(v.z, v.w);
}

// ---------------- prep: W^T + fp16 hi/lo split --------------------------------
__global__ void whalf_kernel(const float* __restrict__ W) {
    __shared__ float t[32][33];
    int bx = blockIdx.x * 32;   // d
    int by = blockIdx.y * 32;   // j
    int tx = threadIdx.x, ty0 = threadIdx.y;
#pragma unroll
    for (int i = 0; i < 4; i++) {
        int ty = ty0 + i * 8;
        t[ty][tx] = W[(size_t)(by + ty) * DIM + bx + tx];
    }
    __syncthreads();
#pragma unroll
    for (int i = 0; i < 4; i++) {
        int ty = ty0 + i * 8;
        float v = t[tx][ty];                     // = W[by+tx][bx+ty]
        __half h = __float2half_rn(v);
        __half l = __float2half_rn(v - __half2float(h));
        size_t o = (size_t)(bx + ty) * DIM + by + tx;   // [d][j]
        g_w16h[o] = h;
        g_w16l[o] = l;
    }
}

// ---------------- prep: keys -> bf16 hi/lo split ------------------------------
__global__ __launch_bounds__(256) void ksplit_kernel(const float* __restrict__ src) {
    size_t i = (size_t)blockIdx.x * 256 + threadIdx.x;
    float4 v = ((const float4*)src)[i];
    __nv_bfloat16 hx = __float2bfloat16(v.x), hy = __float2bfloat16(v.y);
    __nv_bfloat16 hz = __float2bfloat16(v.z), hw = __float2bfloat16(v.w);
    __nv_bfloat16 lx = __float2bfloat16(v.x - __bfloat162float(hx));
    __nv_bfloat16 ly = __float2bfloat16(v.y - __bfloat162float(hy));
    __nv_bfloat16 lz = __float2bfloat16(v.z - __bfloat162float(hz));
    __nv_bfloat16 lw = __float2bfloat16(v.w - __bfloat162float(hw));
    ((__nv_bfloat162*)g_khi)[2 * i]     = __halves2bfloat162(hx, hy);
    ((__nv_bfloat162*)g_khi)[2 * i + 1] = __halves2bfloat162(hz, hw);
    ((__nv_bfloat162*)g_klo)[2 * i]     = __halves2bfloat162(lx, ly);
    ((__nv_bfloat162*)g_klo)[2 * i + 1] = __halves2bfloat162(lz, lw);
}

// ---------------- fp16 2-term GEMM: QT = Q @ W  (3-stage pipeline) ------------
#define KC    32
#define GSTR  80
#define GTILE (128 * GSTR)
#define OFF_A  0
#define OFF_BH GTILE
#define OFF_BL (2 * GTILE)
#define STG   (3 * GTILE)        // 30720 per stage
#define NSTAGE 3
#define SMEM_G (NSTAGE * STG)    // 92160
#define NCHG  (DIM / KC)         // 32

__device__ __forceinline__ void load_stage(uint32_t sst, const __half* a,
                                           const __half* bh, const __half* bl,
                                           int kc0, int tid) {
#pragma unroll
    for (int i = 0; i < 2; i++) {
        int flat = tid + i * 256;
        int r = flat >> 2, seg = flat & 3;
        size_t go = (size_t)r * DIM + kc0 + seg * 8;
        uint32_t so = (uint32_t)(r * GSTR + seg * 16);
        CP_ASYNC16(sst + OFF_A + so, a + go);
        CP_ASYNC16(sst + OFF_BH + so, bh + go);
        CP_ASYNC16(sst + OFF_BL + so, bl + go);
    }
}

__global__ __launch_bounds__(256, 2) void qt_gemm_kernel() {
    extern __shared__ __align__(128) char smem[];
    const int tid  = threadIdx.x;
    const int wid  = tid >> 5, lane = tid & 31;
    const int bn   = blockIdx.x * 128;
    const int bm   = blockIdx.y * 128;
    const int wm   = (wid >> 2) * 64;
    const int wn   = (wid & 3) * 32;
    const uint32_t sb = smem_u32(smem);

    const __half* qa = g_q16  + (size_t)bm * DIM;
    const __half* wh = g_w16h + (size_t)bn * DIM;
    const __half* wl = g_w16l + (size_t)bn * DIM;

    float acc[4][4][4];
#pragma unroll
    for (int i = 0; i < 4; i++)
#pragma unroll
        for (int j = 0; j < 4; j++)
#pragma unroll
            for (int k = 0; k < 4; k++) acc[i][j][k] = 0.f;

    const uint32_t lmo = (uint32_t)((lane & 15) * GSTR + (lane >> 4) * 16);

    // prologue: 2 stages in flight
    load_stage(sb + 0 * STG, qa, wh, wl, 0, tid);
    CP_COMMIT();
    load_stage(sb + 1 * STG, qa, wh, wl, KC, tid);
    CP_COMMIT();

    int sidx = 0;   // stage of chunk c
    for (int c = 0; c < NCHG; c++) {
        if (c + 1 < NCHG) CP_WAIT1(); else CP_WAIT0();   // chunk c data resident
        __syncthreads();                                 // all warps done with the stage being refilled

        // prefetch chunk c+2 into stage (sidx+2)%3 (last read in chunk c-1)
        if (c + 2 < NCHG) {
            int ps = sidx + 2; if (ps >= NSTAGE) ps -= NSTAGE;
            load_stage(sb + ps * STG, qa, wh, wl, (c + 2) * KC, tid);
            CP_COMMIT();
        }

        const uint32_t sst = sb + sidx * STG;
        const uint32_t aB = sst + OFF_A + wm * GSTR + lmo;
        const uint32_t bH = sst + OFF_BH + wn * GSTR + lmo;
        const uint32_t bL = sst + OFF_BL + wn * GSTR + lmo;

#pragma unroll
        for (int kk = 0; kk < 2; kk++) {
            const uint32_t ko = kk * 32;
            uint32_t af[4][4], bh2[2][4], bl2[2][4];
#pragma unroll
            for (int mi = 0; mi < 4; mi++)
                ldsm_x4(aB + mi * (16 * GSTR) + ko, af[mi][0], af[mi][1], af[mi][2], af[mi][3]);
#pragma unroll
            for (int ni = 0; ni < 2; ni++)
                ldsm_x4(bH + ni * (16 * GSTR) + ko, bh2[ni][0], bh2[ni][1], bh2[ni][2], bh2[ni][3]);
#pragma unroll
            for (int ni = 0; ni < 2; ni++)
                ldsm_x4(bL + ni * (16 * GSTR) + ko, bl2[ni][0], bl2[ni][1], bl2[ni][2], bl2[ni][3]);
#pragma unroll
            for (int mi = 0; mi < 4; mi++)
#pragma unroll
                for (int g = 0; g < 4; g++) {
                    int ni = g >> 1, p = g & 1;
                    mma16816h(acc[mi][g], af[mi], bh2[ni][p], bh2[ni][2 + p]);
                }
#pragma unroll
            for (int mi = 0; mi < 4; mi++)
#pragma unroll
                for (int g = 0; g < 4; g++) {
                    int ni = g >> 1, p = g & 1;
                    mma16816h(acc[mi][g], af[mi], bl2[ni][p], bl2[ni][2 + p]);
                }
        }
        sidx++; if (sidx >= NSTAGE) sidx -= NSTAGE;
    }

    const int qr = lane >> 2, qc = (lane & 3) * 2;
#pragma unroll
    for (int mi = 0; mi < 4; mi++) {
#pragma unroll
        for (int g = 0; g < 4; g++) {
            const int col = bn + wn + g * 8 + qc;
#pragma unroll
            for (int half = 0; half < 2; half++) {
                const int row = bm + wm + mi * 16 + qr + half * 8;
                float v0 = acc[mi][g][half * 2], v1 = acc[mi][g][half * 2 + 1];
                __nv_bfloat16 h0 = __float2bfloat16(v0);
                __nv_bfloat16 h1 = __float2bfloat16(v1);
                __nv_bfloat16 l0 = __float2bfloat16(v0 - __bfloat162float(h0));
                __nv_bfloat16 l1 = __float2bfloat16(v1 - __bfloat162float(h1));
                size_t o = ((size_t)row * DIM + col) / 2;
                ((__nv_bfloat162*)g_qthi)[o] = __halves2bfloat162(h0, h1);
                ((__nv_bfloat162*)g_qtlo)[o] = __halves2bfloat162(l0, l1);
            }
        }
    }
}

// ---------------- windowed banded attention (validated R8) --------------------
#define QB3  64
#define KS3  144           // bytes per 64-elem row (+16B pad)
#define SS3  68            // S row stride (floats)
#define PS3  72            // P row stride (bf16 elems) = 144 B

#define O3_KH 0u
#define O3_KL 16128u       // 112*144
#define O3_QH 32256u
#define O3_QL 41472u       // +64*144
#define O3_S  0u           // overlays K (dead when S materialized)
#define O3_PH 32256u       // overlays QT (dead after phase 1)
#define O3_PL 41472u
#define SMEM_B3 50688u

__device__ __forceinline__ void load_k3(uint32_t sb, int q0, size_t kbase,
                                        int dc, int tid) {
    // 112 rows x 8 segs (16B) per plane = 896 flats
#pragma unroll
    for (int i = 0; i < 4; i++) {
        int flat = tid + i * 256;
        if (flat < 896) {
            int r = flat >> 3, seg = flat & 7;
            int kr = q0 - 24 + r;
            uint32_t sh = sb + O3_KH + (uint32_t)(r * KS3 + seg * 16);
            uint32_t sl = sb + O3_KL + (uint32_t)(r * KS3 + seg * 16);
            if ((unsigned)kr < SLEN) {
                size_t go = kbase + (size_t)kr * DIM + dc + seg * 8;
                CP_ASYNC16(sh, g_khi + go);
                CP_ASYNC16(sl, g_klo + go);
            } else {
                ST_SHARED_ZERO16(sh);
                ST_SHARED_ZERO16(sl);
            }
        }
    }
}

__global__ __launch_bounds__(256, 2) void band_attn_kernel(float* __restrict__ out) {
    extern __shared__ __align__(128) char smem[];
    const uint32_t sb = smem_u32(smem);
    const int tid = threadIdx.x, wid = tid >> 5, lane = tid & 31;
    const int b = blockIdx.y, q0 = blockIdx.x * QB3;
    const size_t kbase  = (size_t)b * SLEN * DIM;
    const size_t qtbase = ((size_t)b * SLEN + q0) * DIM;

    const int g  = wid >> 1;      // query group 0..3
    const int hw = wid & 1;       // half (S: window cols; AV: d cols)

    // ---------------- phase 1: S (16x64 per group, 3-term bf16) -------------
    float sacc[4][4];
#pragma unroll
    for (int i = 0; i < 4; i++)
#pragma unroll
        for (int j = 0; j < 4; j++) sacc[i][j] = 0.f;

    const uint32_t lmA = (uint32_t)((16 * g + (lane & 15)) * KS3 + (lane >> 4) * 16);
    const uint32_t lmB = (uint32_t)((16 * g + 32 * hw + (lane & 15)) * KS3 + (lane >> 4) * 16);

    for (int ch = 0; ch < 16; ch++) {
        const int dc = ch * 64;
        // QT tiles: 64 rows x 8 segs per plane = 512 flats
#pragma unroll
        for (int i = 0; i < 2; i++) {
            int flat = tid + i * 256;
            int r = flat >> 3, seg = flat & 7;
            size_t go = qtbase + (size_t)r * DIM + dc + seg * 8;
            uint32_t so = (uint32_t)(r * KS3 + seg * 16);
            CP_ASYNC16(sb + O3_QH + so, g_qthi + go);
            CP_ASYNC16(sb + O3_QL + so, g_qtlo + go);
        }
        load_k3(sb, q0, kbase, dc, tid);
        CP_COMMIT();
        CP_WAIT0();
        __syncthreads();

#pragma unroll
        for (int ks = 0; ks < 4; ks++) {
            const uint32_t ko = ks * 32;
            uint32_t ah[4], al[4], bh[2][4], bl[2][4];
            ldsm_x4(sb + O3_QH + lmA + ko, ah[0], ah[1], ah[2], ah[3]);
            ldsm_x4(sb + O3_QL + lmA + ko, al[0], al[1], al[2], al[3]);
#pragma unroll
            for (int nb = 0; nb < 2; nb++) {
                uint32_t ba = lmB + (uint32_t)(nb * 16 * KS3) + ko;
                ldsm_x4(sb + O3_KH + ba, bh[nb][0], bh[nb][1], bh[nb][2], bh[nb][3]);
                ldsm_x4(sb + O3_KL + ba, bl[nb][0], bl[nb][1], bl[nb][2], bl[nb][3]);
            }
#pragma unroll
            for (int nf = 0; nf < 4; nf++) {
                int nb = nf >> 1, p = nf & 1;
                mma16816(sacc[nf], ah, bh[nb][p], bh[nb][2 + p]);
            }
#pragma unroll
            for (int nf = 0; nf < 4; nf++) {
                int nb = nf >> 1, p = nf & 1;
                mma16816(sacc[nf], ah, bl[nb][p], bl[nb][2 + p]);
            }
#pragma unroll
            for (int nf = 0; nf < 4; nf++) {
                int nb = nf >> 1, p = nf & 1;
                mma16816(sacc[nf], al, bh[nb][p], bh[nb][2 + p]);
            }
        }
        __syncthreads();
    }

    // ---------------- S frags -> smem ---------------------------------------
    {
        float* S = (float*)(smem + O3_S);
        int r0 = 16 * g + (lane >> 2);
        int c0 = 32 * hw + (lane & 3) * 2;
#pragma unroll
        for (int nf = 0; nf < 4; nf++) {
            int c = c0 + nf * 8;
            *(float2*)&S[r0 * SS3 + c]       = make_float2(sacc[nf][0], sacc[nf][1]);
            *(float2*)&S[(r0 + 8) * SS3 + c] = make_float2(sacc[nf][2], sacc[nf][3]);
        }
    }
    __syncthreads();

    // ---------------- softmax over each row's 64-col window ------------------
    if (tid < 128) {
        float* S = (float*)(smem + O3_S);
        __nv_bfloat16* PH = (__nv_bfloat16*)(smem + O3_PH);
        __nv_bfloat16* PL = (__nv_bfloat16*)(smem + O3_PL);
        const int row = tid >> 1, half = tid & 1;
        const int rm = row & 15;
        const int w0 = q0 + (row & ~15) - 24;     // window start (global key)
        int cmin = rm + 4;
        { int t = -w0;            if (t > cmin) cmin = t; }
        int cmax = rm + 44;
        { int t = SLEN - 1 - w0;  if (t < cmax) cmax = t; }
        const int cbeg = half * 32, cend = cbeg + 32;

        float mx = -3.4e38f;
        for (int c = cbeg; c < cend; c++)
            if (c >= cmin && c <= cmax) mx = fmaxf(mx, S[row * SS3 + c]);
        mx = fmaxf(mx, __shfl_xor_sync(0xFFFFFFFFu, mx, 1));

        float sum = 0.f;
        for (int c = cbeg; c < cend; c++) {
            float e = (c >= cmin && c <= cmax) ? __expf(S[row * SS3 + c] - mx) : 0.f;
            S[row * SS3 + c] = e;
            sum += e;
        }
        sum += __shfl_xor_sync(0xFFFFFFFFu, sum, 1);
        const float inv = 1.f / sum;

        for (int c = cbeg; c < cend; c++) {
            float p = S[row * SS3 + c] * inv;
            __nv_bfloat16 h = __float2bfloat16(p);
            __nv_bfloat16 l = __float2bfloat16(p - __bfloat162float(h));
            PH[row * PS3 + c] = h;
            PL[row * PS3 + c] = l;
        }
    }
    __syncthreads();

    // ---------------- phase 3: O = P . K over 64-key windows -----------------
    const uint32_t lmP = (uint32_t)((16 * g + (lane & 15)) * KS3 + (lane >> 4) * 16);
    for (int ch = 0; ch < 16; ch++) {
        const int dc = ch * 64;
        load_k3(sb, q0, kbase, dc, tid);
        CP_COMMIT();
        CP_WAIT0();
        __syncthreads();

        float oacc[4][4];
#pragma unroll
        for (int i = 0; i < 4; i++)
#pragma unroll
            for (int j = 0; j < 4; j++) oacc[i][j] = 0.f;

#pragma unroll
        for (int ks = 0; ks < 4; ks++) {
            const uint32_t ko = ks * 32;
            uint32_t ah[4], al[4], bh[2][4], bl[2][4];
            ldsm_x4(sb + O3_PH + lmP + ko, ah[0], ah[1], ah[2], ah[3]);
            ldsm_x4(sb + O3_PL + lmP + ko, al[0], al[1], al[2], al[3]);
#pragma unroll
            for (int ds = 0; ds < 2; ds++) {
                uint32_t ba = (uint32_t)((16 * g + ks * 16 + (lane & 15)) * KS3 +
                                         64 * hw + ds * 32 + (lane >> 4) * 16);
                ldsm_x4_t(sb + O3_KH + ba, bh[ds][0], bh[ds][1], bh[ds][2], bh[ds][3]);
                ldsm_x4_t(sb + O3_KL + ba, bl[ds][0], bl[ds][1], bl[ds][2], bl[ds][3]);
            }
#pragma unroll
            for (int nf = 0; nf < 4; nf++) {
                int ds = nf >> 1, p = nf & 1;
                mma16816(oacc[nf], ah, bh[ds][2 * p], bh[ds][2 * p + 1]);
            }
#pragma unroll
            for (int nf = 0; nf < 4; nf++) {
                int ds = nf >> 1, p = nf & 1;
                mma16816(oacc[nf], ah, bl[ds][2 * p], bl[ds][2 * p + 1]);
            }
#pragma unroll
            for (int nf = 0; nf < 4; nf++) {
                int ds = nf >> 1, p = nf & 1;
                mma16816(oacc[nf], al, bh[ds][2 * p], bh[ds][2 * p + 1]);
            }
        }

        const int r0 = q0 + 16 * g + (lane >> 2);
        const int c0 = dc + 32 * hw + (lane & 3) * 2;
#pragma unroll
        for (int nf = 0; nf < 4; nf++) {
            int c = c0 + nf * 8;
            *(float2*)(out + kbase + (size_t)r0 * DIM + c) =
                make_float2(oacc[nf][0], oacc[nf][1]);
            *(float2*)(out + kbase + (size_t)(r0 + 8) * DIM + c) =
                make_float2(oacc[nf][2], oacc[nf][3]);
        }
        __syncthreads();
    }
}

extern "C" void kernel_launch(void* const* d_in, const int* in_sizes, int n_in,
                              void* d_out, int out_size) {
    const float* queries = (const float*)d_in[0];
    const float* keys    = (const float*)d_in[1];
    const float* W       = (const float*)d_in[2];
    // d_in[3] = b_reduce: per-(b,q) constant added to all logits -> softmax-invariant, unused.
    float* out = (float*)d_out;

    cudaFuncSetAttribute(qt_gemm_kernel, cudaFuncAttributeMaxDynamicSharedMemorySize, SMEM_G);
    cudaFuncSetAttribute(band_attn_kernel, cudaFuncAttributeMaxDynamicSharedMemorySize, SMEM_B3);

    const int elemGrid = (MTOT * DIM) / 4 / 256;
    qhalf_kernel<<<elemGrid, 256>>>(queries);
    ksplit_kernel<<<elemGrid, 256>>>(keys);
    whalf_kernel<<<dim3(DIM / 32, DIM / 32), dim3(32, 8)>>>(W);

    dim3 gg(DIM / 128, MTOT / 128);
    qt_gemm_kernel<<<gg, 256, SMEM_G>>>();

    dim3 g2(SLEN / QB3, BATCH);
    band_attn_kernel<<<g2, 256, SMEM_B3>>>(out);
}

// round 14
// speedup vs baseline: 2.7402x; 1.0766x over previous
// Round 14.
//
// R13 post-mortem: finally benched; rel_err 1.200e-3 FAIL (threshold 1e-3).
// Attribution: the band kernel's in-kernel K conversion is bit-identical to the old
// ksplit kernel (same __floats2bfloat162_rn ops), so the error regression is entirely
// the GEMM fp16-accumulator probe. My 1.6e-4 noise estimate was ~8x low: fp16-acc
// HMMA rounds the running sum to fp16 every step (ULP ~2^-13 at partial-sum magnitudes
// ~0.3-1.0 over k=16 chains x 64 chunk-drains), giving ~4e-4..1e-3 extra logit noise
// -> total 1.2e-3. Conclusion recorded: fp16-acc mma is numerically unusable here at
// the current 5e-3 logit-error budget; probe abandoned (its speed was never measured,
// but it cannot be used regardless).
//
// R14 = revert GEMM to the validated R9 engine (fp16 2-term, f32-acc, 3-stage
// cp.async pipeline; measured 226us, rel_err 7.7306e-4) + keep R13's band kernel
// (ksplit prep kernel eliminated -> saves its ~10us + 128MB DRAM round-trip;
// register-prefetched in-kernel K f32->bf16 hi/lo conversion; double-buffered QT
// stage; K(ch+1) LDG prefetch overlapping compute).
//
// Prediction: preps ~12us + GEMM ~226us + band ~70-85us (was ~105 incl. ksplit)
// -> total ~310-325us (beats 344.1). rel_err exactly 7.7306e-4 (GEMM numerics
// identical to R8/R9; band drops only exact-zero products and converts K with
// identical rounding). If band lands >90us, the LDG->STS conversion path is
// costing more than the cp.async path saved and R15 re-evaluates with ncu.

#include <cuda_runtime.h>
#include <cuda_bf16.h>
#include <cuda_fp16.h>
#include <cstdint>

#define BATCH 8
#define SLEN  2048
#define DIM   1024
#define WIN   20
#define MTOT  (BATCH * SLEN)

__device__ __half        g_q16 [(size_t)MTOT * DIM];
__device__ __half        g_w16h[(size_t)DIM * DIM];
__device__ __half        g_w16l[(size_t)DIM * DIM];
__device__ __nv_bfloat16 g_qthi[(size_t)MTOT * DIM];
__device__ __nv_bfloat16 g_qtlo[(size_t)MTOT * DIM];

__device__ __forceinline__ uint32_t smem_u32(const void* p) {
    uint32_t a;
    asm("{ .reg .u64 t; cvta.to.shared.u64 t, %1; cvt.u32.u64 %0, t; }" : "=r"(a) : "l"(p));
    return a;
}
#define CP_ASYNC16(sd, gp) \
    asm volatile("cp.async.cg.shared.global [%0], [%1], 16;" :: "r"(sd), "l"(gp) : "memory")
#define CP_COMMIT()   asm volatile("cp.async.commit_group;" ::: "memory")
#define CP_WAIT0()    asm volatile("cp.async.wait_group 0;" ::: "memory")
#define CP_WAIT1()    asm volatile("cp.async.wait_group 1;" ::: "memory")
#define STS128(a, r0, r1, r2, r3) \
    asm volatile("st.shared.v4.b32 [%0], {%1,%2,%3,%4};" \
                 :: "r"(a), "r"(r0), "r"(r1), "r"(r2), "r"(r3) : "memory")

__device__ __forceinline__ void ldsm_x4(uint32_t a, uint32_t& r0, uint32_t& r1,
                                        uint32_t& r2, uint32_t& r3) {
    asm volatile("ldmatrix.sync.aligned.m8n8.x4.shared.b16 {%0,%1,%2,%3}, [%4];"
                 : "=r"(r0), "=r"(r1), "=r"(r2), "=r"(r3) : "r"(a));
}
__device__ __forceinline__ void ldsm_x4_t(uint32_t a, uint32_t& r0, uint32_t& r1,
                                          uint32_t& r2, uint32_t& r3) {
    asm volatile("ldmatrix.sync.aligned.m8n8.x4.trans.shared.b16 {%0,%1,%2,%3}, [%4];"
                 : "=r"(r0), "=r"(r1), "=r"(r2), "=r"(r3) : "r"(a));
}
__device__ __forceinline__ void mma16816(float* c, const uint32_t* a,
                                         uint32_t b0, uint32_t b1) {
    asm volatile(
        "mma.sync.aligned.m16n8k16.row.col.f32.bf16.bf16.f32 "
        "{%0,%1,%2,%3}, {%4,%5,%6,%7}, {%8,%9}, {%0,%1,%2,%3};"
        : "+f"(c[0]), "+f"(c[1]), "+f"(c[2]), "+f"(c[3])
        : "r"(a[0]), "r"(a[1]), "r"(a[2]), "r"(a[3]), "r"(b0), "r"(b1));
}
__device__ __forceinline__ void mma16816h(float* c, const uint32_t* a,
                                          uint32_t b0, uint32_t b1) {
    asm volatile(
        "mma.sync.aligned.m16n8k16.row.col.f32.f16.f16.f32 "
        "{%0,%1,%2,%3}, {%4,%5,%6,%7}, {%8,%9}, {%0,%1,%2,%3};"
        : "+f"(c[0]), "+f"(c[1]), "+f"(c[2]), "+f"(c[3])
        : "r"(a[0]), "r"(a[1]), "r"(a[2]), "r"(a[3]), "r"(b0), "r"(b1));
}

__global__ __launch_bounds__(256) void qhalf_kernel(const float* __restrict__ Q) {
    size_t i = (size_t)blockIdx.x * 256 + threadIdx.x;
    float4 v = ((const float4*)Q)[i];
    ((__half2*)g_q16)[2 * i]     = __floats2half2_rn(v.x, v.y);
    ((__half2*)g_q16)[2 * i + 1] = __floats2half2_rn(v.z, v.w);
}

__global__ void whalf_kernel(const float* __restrict__ W) {
    __shared__ float t[32][33];
    int bx = blockIdx.x * 32;
    int by = blockIdx.y * 32;
    int tx = threadIdx.x, ty0 = threadIdx.y;
#pragma unroll
    for (int i = 0; i < 4; i++) {
        int ty = ty0 + i * 8;
        t[ty][tx] = W[(size_t)(by + ty) * DIM + bx + tx];
    }
    __syncthreads();
#pragma unroll
    for (int i = 0; i < 4; i++) {
        int ty = ty0 + i * 8;
        float v = t[tx][ty];
        __half h = __float2half_rn(v);
        __half l = __float2half_rn(v - __half2float(h));
        size_t o = (size_t)(bx + ty) * DIM + by + tx;
        g_w16h[o] = h;
        g_w16l[o] = l;
    }
}

// ---- fp16 2-term GEMM (validated R9: f32 accumulators, 3-stage pipeline) ----
#define KC    32
#define GSTR  80
#define GTILE (128 * GSTR)
#define OFF_A  0
#define OFF_BH GTILE
#define OFF_BL (2 * GTILE)
#define STG   (3 * GTILE)
#define NSTAGE 3
#define SMEM_G (NSTAGE * STG)
#define NCHG  (DIM / KC)

__device__ __forceinline__ void load_stage(uint32_t sst, const __half* a,
                                           const __half* bh, const __half* bl,
                                           int kc0, int tid) {
#pragma unroll
    for (int i = 0; i < 2; i++) {
        int flat = tid + i * 256;
        int r = flat >> 2, seg = flat & 3;
        size_t go = (size_t)r * DIM + kc0 + seg * 8;
        uint32_t so = (uint32_t)(r * GSTR + seg * 16);
        CP_ASYNC16(sst + OFF_A + so, a + go);
        CP_ASYNC16(sst + OFF_BH + so, bh + go);
        CP_ASYNC16(sst + OFF_BL + so, bl + go);
    }
}

__global__ __launch_bounds__(256, 2) void qt_gemm_kernel() {
    extern __shared__ __align__(128) char smem[];
    const int tid  = threadIdx.x;
    const int wid  = tid >> 5, lane = tid & 31;
    const int bn   = blockIdx.x * 128;
    const int bm   = blockIdx.y * 128;
    const int wm   = (wid >> 2) * 64;
    const int wn   = (wid & 3) * 32;
    const uint32_t sb = smem_u32(smem);

    const __half* qa = g_q16  + (size_t)bm * DIM;
    const __half* wh = g_w16h + (size_t)bn * DIM;
    const __half* wl = g_w16l + (size_t)bn * DIM;

    float acc[4][4][4];
#pragma unroll
    for (int i = 0; i < 4; i++)
#pragma unroll
        for (int j = 0; j < 4; j++)
#pragma unroll
            for (int k = 0; k < 4; k++) acc[i][j][k] = 0.f;

    const uint32_t lmo = (uint32_t)((lane & 15) * GSTR + (lane >> 4) * 16);

    load_stage(sb + 0 * STG, qa, wh, wl, 0, tid);
    CP_COMMIT();
    load_stage(sb + 1 * STG, qa, wh, wl, KC, tid);
    CP_COMMIT();

    int sidx = 0;
    for (int c = 0; c < NCHG; c++) {
        if (c + 1 < NCHG) CP_WAIT1(); else CP_WAIT0();
        __syncthreads();

        if (c + 2 < NCHG) {
            int ps = sidx + 2; if (ps >= NSTAGE) ps -= NSTAGE;
            load_stage(sb + ps * STG, qa, wh, wl, (c + 2) * KC, tid);
            CP_COMMIT();
        }

        const uint32_t sst = sb + sidx * STG;
        const uint32_t aB = sst + OFF_A + wm * GSTR + lmo;
        const uint32_t bH = sst + OFF_BH + wn * GSTR + lmo;
        const uint32_t bL = sst + OFF_BL + wn * GSTR + lmo;

#pragma unroll
        for (int kk = 0; kk < 2; kk++) {
            const uint32_t ko = kk * 32;
            uint32_t af[4][4], bh2[2][4], bl2[2][4];
#pragma unroll
            for (int mi = 0; mi < 4; mi++)
                ldsm_x4(aB + mi * (16 * GSTR) + ko, af[mi][0], af[mi][1], af[mi][2], af[mi][3]);
#pragma unroll
            for (int ni = 0; ni < 2; ni++)
                ldsm_x4(bH + ni * (16 * GSTR) + ko, bh2[ni][0], bh2[ni][1], bh2[ni][2], bh2[ni][3]);
#pragma unroll
            for (int ni = 0; ni < 2; ni++)
                ldsm_x4(bL + ni * (16 * GSTR) + ko, bl2[ni][0], bl2[ni][1], bl2[ni][2], bl2[ni][3]);
#pragma unroll
            for (int mi = 0; mi < 4; mi++)
#pragma unroll
                for (int g2 = 0; g2 < 4; g2++) {
                    int ni = g2 >> 1, p = g2 & 1;
                    mma16816h(acc[mi][g2], af[mi], bh2[ni][p], bh2[ni][2 + p]);
                }
#pragma unroll
            for (int mi = 0; mi < 4; mi++)
#pragma unroll
                for (int g2 = 0; g2 < 4; g2++) {
                    int ni = g2 >> 1, p = g2 & 1;
                    mma16816h(acc[mi][g2], af[mi], bl2[ni][p], bl2[ni][2 + p]);
                }
        }
        sidx++; if (sidx >= NSTAGE) sidx -= NSTAGE;
    }

    const int qr = lane >> 2, qc = (lane & 3) * 2;
#pragma unroll
    for (int mi = 0; mi < 4; mi++) {
#pragma unroll
        for (int g2 = 0; g2 < 4; g2++) {
            const int col = bn + wn + g2 * 8 + qc;
#pragma unroll
            for (int half = 0; half < 2; half++) {
                const int row = bm + wm + mi * 16 + qr + half * 8;
                float v0 = acc[mi][g2][half * 2], v1 = acc[mi][g2][half * 2 + 1];
                __nv_bfloat16 h0 = __float2bfloat16(v0);
                __nv_bfloat16 h1 = __float2bfloat16(v1);
                __nv_bfloat16 l0 = __float2bfloat16(v0 - __bfloat162float(h0));
                __nv_bfloat16 l1 = __float2bfloat16(v1 - __bfloat162float(h1));
                size_t o = ((size_t)row * DIM + col) / 2;
                ((__nv_bfloat162*)g_qthi)[o] = __halves2bfloat162(h0, h1);
                ((__nv_bfloat162*)g_qtlo)[o] = __halves2bfloat162(l0, l1);
            }
        }
    }
}

// ---- windowed banded attention (R13 band: in-kernel K conversion) ----
#define QB3  64
#define KS3  144
#define SS3  68

#define O3_KH 0u
#define O3_KL 16128u
#define O3_Q0 32256u
#define QSTG  18432u
#define O3_PH 32256u
#define O3_PL 41472u
#define SMEM_B3 69120u

__device__ __forceinline__ void k3_ldg(float4 (&pv)[4][2], const float* __restrict__ keys,
                                       size_t kbase, int q0, int dc, int tid) {
#pragma unroll
    for (int i = 0; i < 4; i++) {
        int flat = tid + i * 256;
        int r = flat >> 3, seg = flat & 7;
        int kr = q0 - 24 + r;
        if (flat < 896 && (unsigned)kr < SLEN) {
            const float4* gp = (const float4*)(keys + kbase + (size_t)kr * DIM + dc + seg * 8);
            pv[i][0] = gp[0];
            pv[i][1] = gp[1];
        } else {
            pv[i][0] = make_float4(0.f, 0.f, 0.f, 0.f);
            pv[i][1] = make_float4(0.f, 0.f, 0.f, 0.f);
        }
    }
}

__device__ __forceinline__ void k3_flush(const float4 (&pv)[4][2], uint32_t sb, int tid) {
#pragma unroll
    for (int i = 0; i < 4; i++) {
        int flat = tid + i * 256;
        if (flat < 896) {
            int r = flat >> 3, seg = flat & 7;
            uint32_t sh = sb + O3_KH + (uint32_t)(r * KS3 + seg * 16);
            uint32_t sl = sb + O3_KL + (uint32_t)(r * KS3 + seg * 16);
            uint32_t hreg[4], lreg[4];
#pragma unroll
            for (int j = 0; j < 2; j++) {
                float4 v = pv[i][j];
                __nv_bfloat162 h0 = __floats2bfloat162_rn(v.x, v.y);
                __nv_bfloat162 h1 = __floats2bfloat162_rn(v.z, v.w);
                float2 b0 = __bfloat1622float2(h0);
                float2 b1 = __bfloat1622float2(h1);
                __nv_bfloat162 l0 = __floats2bfloat162_rn(v.x - b0.x, v.y - b0.y);
                __nv_bfloat162 l1 = __floats2bfloat162_rn(v.z - b1.x, v.w - b1.y);
                hreg[2 * j]     = *(uint32_t*)&h0;
                hreg[2 * j + 1] = *(uint32_t*)&h1;
                lreg[2 * j]     = *(uint32_t*)&l0;
                lreg[2 * j + 1] = *(uint32_t*)&l1;
            }
            STS128(sh, hreg[0], hreg[1], hreg[2], hreg[3]);
            STS128(sl, lreg[0], lreg[1], lreg[2], lreg[3]);
        }
    }
}

__device__ __forceinline__ void qt_cp(uint32_t qdst, size_t qtbase, int dc, int tid) {
#pragma unroll
    for (int i = 0; i < 2; i++) {
        int flat = tid + i * 256;
        int r = flat >> 3, seg = flat & 7;
        size_t go = qtbase + (size_t)r * DIM + dc + seg * 8;
        uint32_t so = (uint32_t)(r * KS3 + seg * 16);
        CP_ASYNC16(qdst + so, g_qthi + go);
        CP_ASYNC16(qdst + 9216u + so, g_qtlo + go);
    }
}

__global__ __launch_bounds__(256, 2) void band_attn_kernel(const float* __restrict__ keys,
                                                           float* __restrict__ out) {
    extern __shared__ __align__(128) char smem[];
    const uint32_t sb = smem_u32(smem);
    const int tid = threadIdx.x, wid = tid >> 5, lane = tid & 31;
    const int b = blockIdx.y, q0 = blockIdx.x * QB3;
    const size_t kbase  = (size_t)b * SLEN * DIM;
    const size_t qtbase = ((size_t)b * SLEN + q0) * DIM;

    const int g  = wid >> 1;
    const int hw = wid & 1;

    float4 pv[4][2];

    float sacc[4][4];
#pragma unroll
    for (int i = 0; i < 4; i++)
#pragma unroll
        for (int j = 0; j < 4; j++) sacc[i][j] = 0.f;

    const uint32_t lmA = (uint32_t)((16 * g + (lane & 15)) * KS3 + (lane >> 4) * 16);
    const uint32_t lmB = (uint32_t)((16 * g + 32 * hw + (lane & 15)) * KS3 + (lane >> 4) * 16);

    k3_ldg(pv, keys, kbase, q0, 0, tid);
    qt_cp(sb + O3_Q0, qtbase, 0, tid);
    CP_COMMIT();

    for (int ch = 0; ch < 16; ch++) {
        const uint32_t qs = sb + O3_Q0 + (uint32_t)(ch & 1) * QSTG;
        k3_flush(pv, sb, tid);
        if (ch + 1 < 16) {
            qt_cp(sb + O3_Q0 + (uint32_t)((ch + 1) & 1) * QSTG, qtbase, (ch + 1) * 64, tid);
            CP_COMMIT();
            k3_ldg(pv, keys, kbase, q0, (ch + 1) * 64, tid);
            CP_WAIT1();
        } else {
            CP_WAIT0();
        }
        __syncthreads();

#pragma unroll
        for (int ks = 0; ks < 4; ks++) {
            const uint32_t ko = ks * 32;
            uint32_t ah[4], al[4], bh[2][4], bl[2][4];
            ldsm_x4(qs + lmA + ko, ah[0], ah[1], ah[2], ah[3]);
            ldsm_x4(qs + 9216u + lmA + ko, al[0], al[1], al[2], al[3]);
#pragma unroll
            for (int nb = 0; nb < 2; nb++) {
                uint32_t ba = lmB + (uint32_t)(nb * 16 * KS3) + ko;
                ldsm_x4(sb + O3_KH + ba, bh[nb][0], bh[nb][1], bh[nb][2], bh[nb][3]);
                ldsm_x4(sb + O3_KL + ba, bl[nb][0], bl[nb][1], bl[nb][2], bl[nb][3]);
            }
#pragma unroll
            for (int nf = 0; nf < 4; nf++) {
                int nb = nf >> 1, p = nf & 1;
                mma16816(sacc[nf], ah, bh[nb][p], bh[nb][2 + p]);
            }
#pragma unroll
            for (int nf = 0; nf < 4; nf++) {
                int nb = nf >> 1, p = nf & 1;
                mma16816(sacc[nf], ah, bl[nb][p], bl[nb][2 + p]);
            }
#pragma unroll
            for (int nf = 0; nf < 4; nf++) {
                int nb = nf >> 1, p = nf & 1;
                mma16816(sacc[nf], al, bh[nb][p], bh[nb][2 + p]);
            }
        }
        __syncthreads();
    }

    // S fragments -> smem (S overlays the K region at offset 0)
    {
        float* S = (float*)smem;
        int r0 = 16 * g + (lane >> 2);
        int c0 = 32 * hw + (lane & 3) * 2;
#pragma unroll
        for (int nf = 0; nf < 4; nf++) {
            int c = c0 + nf * 8;
            *(float2*)&S[r0 * SS3 + c]       = make_float2(sacc[nf][0], sacc[nf][1]);
            *(float2*)&S[(r0 + 8) * SS3 + c] = make_float2(sacc[nf][2], sacc[nf][3]);
        }
    }
    __syncthreads();

    // prefetch phase-3 K(0) while softmax runs
    k3_ldg(pv, keys, kbase, q0, 0, tid);

    if (tid < 128) {
        float* S = (float*)smem;
        __nv_bfloat16* PH = (__nv_bfloat16*)(smem + O3_PH);
        __nv_bfloat16* PL = (__nv_bfloat16*)(smem + O3_PL);
        const int row = tid >> 1, half = tid & 1;
        const int rm = row & 15;
        const int w0 = q0 + (row & ~15) - 24;
        int cmin = rm + 4;
        { int t = -w0;            if (t > cmin) cmin = t; }
        int cmax = rm + 44;
        { int t = SLEN - 1 - w0;  if (t < cmax) cmax = t; }
        const int cbeg = half * 32, cend = cbeg + 32;

        float mx = -3.4e38f;
        for (int c = cbeg; c < cend; c++)
            if (c >= cmin && c <= cmax) mx = fmaxf(mx, S[row * SS3 + c]);
        mx = fmaxf(mx, __shfl_xor_sync(0xFFFFFFFFu, mx, 1));

        float sum = 0.f;
        for (int c = cbeg; c < cend; c++) {
            float e = (c >= cmin && c <= cmax) ? __expf(S[row * SS3 + c] - mx) : 0.f;
            S[row * SS3 + c] = e;
            sum += e;
        }
        sum += __shfl_xor_sync(0xFFFFFFFFu, sum, 1);
        const float inv = 1.f / sum;

        for (int c = cbeg; c < cend; c++) {
            float p = S[row * SS3 + c] * inv;
            __nv_bfloat16 h = __float2bfloat16(p);
            __nv_bfloat16 l = __float2bfloat16(p - __bfloat162float(h));
            PH[row * 72 + c] = h;
            PL[row * 72 + c] = l;
        }
    }
    __syncthreads();

    const uint32_t lmP = (uint32_t)((16 * g + (lane & 15)) * KS3 + (lane >> 4) * 16);
    for (int ch = 0; ch < 16; ch++) {
        const int dc = ch * 64;
        k3_flush(pv, sb, tid);
        if (ch + 1 < 16)
            k3_ldg(pv, keys, kbase, q0, (ch + 1) * 64, tid);
        __syncthreads();

        float oacc[4][4];
#pragma unroll
        for (int i = 0; i < 4; i++)
#pragma unroll
            for (int j = 0; j < 4; j++) oacc[i][j] = 0.f;

#pragma unroll
        for (int ks = 0; ks < 4; ks++) {
            const uint32_t ko = ks * 32;
            uint32_t ah[4], al[4], bh[2][4], bl[2][4];
            ldsm_x4(sb + O3_PH + lmP + ko, ah[0], ah[1], ah[2], ah[3]);
            ldsm_x4(sb + O3_PL + lmP + ko, al[0], al[1], al[2], al[3]);
#pragma unroll
            for (int ds = 0; ds < 2; ds++) {
                uint32_t ba = (uint32_t)((16 * g + ks * 16 + (lane & 15)) * KS3 +
                                         64 * hw + ds * 32 + (lane >> 4) * 16);
                ldsm_x4_t(sb + O3_KH + ba, bh[ds][0], bh[ds][1], bh[ds][2], bh[ds][3]);
                ldsm_x4_t(sb + O3_KL + ba, bl[ds][0], bl[ds][1], bl[ds][2], bl[ds][3]);
            }
#pragma unroll
            for (int nf = 0; nf < 4; nf++) {
                int ds = nf >> 1, p = nf & 1;
                mma16816(oacc[nf], ah, bh[ds][2 * p], bh[ds][2 * p + 1]);
            }
#pragma unroll
            for (int nf = 0; nf < 4; nf++) {
                int ds = nf >> 1, p = nf & 1;
                mma16816(oacc[nf], ah, bl[ds][2 * p], bl[ds][2 * p + 1]);
            }
#pragma unroll
            for (int nf = 0; nf < 4; nf++) {
                int ds = nf >> 1, p = nf & 1;
                mma16816(oacc[nf], al, bh[ds][2 * p], bh[ds][2 * p + 1]);
            }
        }

        const int r0 = q0 + 16 * g + (lane >> 2);
        const int c0 = dc + 32 * hw + (lane & 3) * 2;
#pragma unroll
        for (int nf = 0; nf < 4; nf++) {
            int c = c0 + nf * 8;
            *(float2*)(out + kbase + (size_t)r0 * DIM + c) =
                make_float2(oacc[nf][0], oacc[nf][1]);
            *(float2*)(out + kbase + (size_t)(r0 + 8) * DIM + c) =
                make_float2(oacc[nf][2], oacc[nf][3]);
        }
        __syncthreads();
    }
}

extern "C" void kernel_launch(void* const* d_in, const int* in_sizes, int n_in,
                              void* d_out, int out_size) {
    const float* queries = (const float*)d_in[0];
    const float* keys    = (const float*)d_in[1];
    const float* W       = (const float*)d_in[2];
    // d_in[3] = b_reduce: per-(b,q) constant added to all logits -> softmax-invariant, unused.
    float* out = (float*)d_out;

    cudaFuncSetAttribute(qt_gemm_kernel, cudaFuncAttributeMaxDynamicSharedMemorySize, SMEM_G);
    cudaFuncSetAttribute(band_attn_kernel, cudaFuncAttributeMaxDynamicSharedMemorySize, SMEM_B3);

    const int elemGrid = (MTOT * DIM) / 4 / 256;
    qhalf_kernel<<<elemGrid, 256>>>(queries);
    whalf_kernel<<<dim3(DIM / 32, DIM / 32), dim3(32, 8)>>>(W);

    dim3 gg(DIM / 128, MTOT / 128);
    qt_gemm_kernel<<<gg, 256, SMEM_G>>>();

    dim3 g2(SLEN / QB3, BATCH);
    band_attn_kernel<<<g2, 256, SMEM_B3>>>(keys, out);
}